// round 11
// baseline (speedup 1.0000x reference)
#include <cuda_runtime.h>
#include <cuda_bf16.h>
#include <cstdint>

#define HD 128
#define MAXN 50000
#define MAXE 800000
#define MAXG 64

// ---------------- scratch (static __device__ arrays; no allocation) ----------
__device__ __align__(16) float g_A   [(size_t)MAXN * HD];
__device__ __align__(16) float g_Bv  [(size_t)MAXN * HD];
__device__ __align__(16) float g_R   [(size_t)MAXN * HD];
__device__ __align__(16) float g_h2  [(size_t)MAXN * HD];
__device__ __align__(16) float g_pool[(size_t)MAXG * HD];
// augmented bf16 activations: [n, 384] = [hi(128) | lo(128) | hi(128)]
__device__ __align__(16) __nv_bfloat16 g_xaug[(size_t)MAXN * 384];
__device__ __align__(16) __nv_bfloat16 g_gaug[(size_t)MAXN * 384];
// augmented weights, [n, k'] row-major
__device__ __align__(16) __nv_bfloat16 g_wabr[2][384 * 384];
__device__ __align__(16) __nv_bfloat16 g_wupd[2][128 * 768];
// CSR scratch
__device__ int   g_deg [MAXN];
__device__ int   g_off [MAXN + 1];
__device__ int   g_cur [MAXN];
__device__ int   g_part[80];
__device__ int   g_srow[MAXE];
__device__ float g_sdst[MAXE];

// ---------------- helpers ----------------------------------------------------
__device__ __forceinline__ void red_add_v4(float* dst, float4 v) {
    asm volatile("red.global.add.v4.f32 [%0], {%1,%2,%3,%4};"
                 :: "l"(dst), "f"(v.x), "f"(v.y), "f"(v.z), "f"(v.w) : "memory");
}
__device__ __forceinline__ uint32_t smem_u32(const void* p) {
    uint32_t a;
    asm("{ .reg .u64 t; cvta.to.shared.u64 t, %1; cvt.u32.u64 %0, t; }"
        : "=r"(a) : "l"(p));
    return a;
}
__device__ __forceinline__ void cp_async16(uint32_t dst, const void* src) {
    asm volatile("cp.async.ca.shared.global [%0], [%1], 16;"
                 :: "r"(dst), "l"(src) : "memory");
}
__device__ __forceinline__ void cp_commit() {
    asm volatile("cp.async.commit_group;" ::: "memory");
}
template <int N>
__device__ __forceinline__ void cp_wait() {
    asm volatile("cp.async.wait_group %0;" :: "n"(N) : "memory");
}
__device__ __forceinline__ void ldmatrix_x4(uint32_t* r, uint32_t addr) {
    asm volatile("ldmatrix.sync.aligned.m8n8.x4.shared.b16 {%0,%1,%2,%3}, [%4];"
                 : "=r"(r[0]), "=r"(r[1]), "=r"(r[2]), "=r"(r[3]) : "r"(addr));
}
__device__ __forceinline__ void mma16816(float* d, const uint32_t* a,
                                         uint32_t b0, uint32_t b1) {
    asm volatile("mma.sync.aligned.m16n8k16.row.col.f32.bf16.bf16.f32 "
                 "{%0,%1,%2,%3}, {%4,%5,%6,%7}, {%8,%9}, {%0,%1,%2,%3};"
                 : "+f"(d[0]), "+f"(d[1]), "+f"(d[2]), "+f"(d[3])
                 : "r"(a[0]), "r"(a[1]), "r"(a[2]), "r"(a[3]),
                   "r"(b0), "r"(b1));
}

// ---------------- bf16 tensor-core GEMM ---------------------------------------
// Block tile 256x128, 8 warps (4m x 2n), warp tile 64x64, BK=32, 3-stage
// cp.async, ldmatrix frags. smem rows padded to 40 bf16 -> conflict-free.
// mode 1 (ABR): K'=384, grid.y: 0->outA, 1->outB(+bias), 2->outR
// mode 2 (UPD): K'=768, out fp32 = resid + relu(acc + bias)
// mode 3 (UPD): same math, write augmented bf16 [hi|lo|hi] to outAug
#define SROW 40
#define BM 256
#define SBUFA (BM * SROW * 2)            // 20480 bytes per stage (A)
#define SBUFW (128 * SROW * 2)           // 10240 bytes per stage (B)
#define STAGES 3
#define GEMM_SMEM (STAGES * (SBUFA + SBUFW))   // 92160 bytes

__device__ __forceinline__ void stage_load(
    int s, int t, int row0, int nrows,
    const __nv_bfloat16* __restrict__ A0, const __nv_bfloat16* __restrict__ A1,
    const __nv_bfloat16* __restrict__ Wp, int wstride,
    uint32_t smbase)
{
    int buf = s % STAGES;
    int kk = (s % 12) * 32;
    int koff = (s / 12) * 384 + kk;
    const __nv_bfloat16* Asrc = (s < 12) ? A0 : A1;
    uint32_t dA = smbase + (uint32_t)buf * SBUFA;
    uint32_t dB = smbase + (uint32_t)(STAGES * SBUFA) + (uint32_t)buf * SBUFW;
    // A: 256 rows x 4 quads = 1024 cp.async, 4 per thread
    #pragma unroll
    for (int i = t * 4; i < t * 4 + 4; i++) {
        int r = i >> 2, q = i & 3;
        int gr = row0 + r; if (gr >= nrows) gr = nrows - 1;
        cp_async16(dA + r * 80 + q * 16, Asrc + (size_t)gr * 384 + kk + q * 8);
    }
    // B: 128 rows x 4 quads = 512 cp.async, 2 per thread
    #pragma unroll
    for (int i = t * 2; i < t * 2 + 2; i++) {
        int r = i >> 2, q = i & 3;
        cp_async16(dB + r * 80 + q * 16, Wp + (size_t)r * wstride + koff + q * 8);
    }
    cp_commit();
}

__global__ void __launch_bounds__(256, 1)
bmma_gemm(const __nv_bfloat16* __restrict__ A0,
          const __nv_bfloat16* __restrict__ A1,
          const __nv_bfloat16* __restrict__ W, int wstride,
          const float* __restrict__ bias, const float* __restrict__ resid,
          float* __restrict__ outA, float* __restrict__ outB,
          float* __restrict__ outR, __nv_bfloat16* __restrict__ outAug,
          int nrows, int mode)
{
    extern __shared__ char smraw[];
    uint32_t smbase = smem_u32(smraw);

    int t = threadIdx.x;
    int warp = t >> 5, lane = t & 31;
    int wm = warp & 3, wn = warp >> 2;       // 4 x 2 warp grid, warp tile 64x64
    int g = lane >> 2, tg = lane & 3;
    int row0 = blockIdx.x * BM;
    const __nv_bfloat16* Wp = W + (size_t)(blockIdx.y * 128) * wstride;

    int nsteps = (mode >= 2) ? 24 : 12;

    float acc[4][8][4];
    #pragma unroll
    for (int i = 0; i < 4; i++)
        #pragma unroll
        for (int j = 0; j < 8; j++)
            #pragma unroll
            for (int k = 0; k < 4; k++) acc[i][j][k] = 0.f;

    uint32_t aLane = (uint32_t)(((lane & 15) * SROW + (lane >> 4) * 8) * 2);
    uint32_t bLane = (uint32_t)((((lane >> 4) * 8 + (lane & 7)) * SROW
                               + ((lane >> 3) & 1) * 8) * 2);

    stage_load(0, t, row0, nrows, A0, A1, Wp, wstride, smbase);
    stage_load(1, t, row0, nrows, A0, A1, Wp, wstride, smbase);

    for (int s = 0; s < nsteps; ++s) {
        cp_wait<1>();
        __syncthreads();
        if (s + 2 < nsteps)
            stage_load(s + 2, t, row0, nrows, A0, A1, Wp, wstride, smbase);
        else
            cp_commit();   // empty group keeps wait<1> semantics uniform

        int buf = s % STAGES;
        uint32_t bufA = smbase + (uint32_t)buf * SBUFA;
        uint32_t bufB = smbase + (uint32_t)(STAGES * SBUFA) + (uint32_t)buf * SBUFW;

        #pragma unroll
        for (int ks = 0; ks < 32; ks += 16) {
            uint32_t aF[4][4];
            #pragma unroll
            for (int mi = 0; mi < 4; mi++)
                ldmatrix_x4(aF[mi],
                    bufA + (uint32_t)(((wm * 64 + mi * 16) * SROW + ks) * 2) + aLane);
            #pragma unroll
            for (int p = 0; p < 4; p++) {
                uint32_t r[4];
                ldmatrix_x4(r,
                    bufB + (uint32_t)(((wn * 64 + p * 16) * SROW + ks) * 2) + bLane);
                #pragma unroll
                for (int mi = 0; mi < 4; mi++) {
                    mma16816(acc[mi][2 * p],     aF[mi], r[0], r[1]);
                    mma16816(acc[mi][2 * p + 1], aF[mi], r[2], r[3]);
                }
            }
        }
        __syncthreads();
    }

    // ---- epilogue ----
    float* dst = outA;
    const float* bi = nullptr;
    const float* rs = nullptr;
    bool dorelu = false;
    if (mode == 1) {
        if (blockIdx.y == 0)      dst = outA;
        else if (blockIdx.y == 1) { dst = outB; bi = bias; }
        else                      dst = outR;
    } else {
        bi = bias; rs = resid; dorelu = true;
    }

    #pragma unroll
    for (int mi = 0; mi < 4; mi++) {
        #pragma unroll
        for (int ni = 0; ni < 8; ni++) {
            int colb = wn * 64 + ni * 8 + tg * 2;
            float bx = 0.f, by = 0.f;
            if (bi) { bx = __ldg(bi + colb); by = __ldg(bi + colb + 1); }
            #pragma unroll
            for (int h = 0; h < 2; h++) {
                int r1 = row0 + wm * 64 + mi * 16 + g + h * 8;
                if (r1 >= nrows) continue;
                float vx = acc[mi][ni][2 * h]     + bx;
                float vy = acc[mi][ni][2 * h + 1] + by;
                if (dorelu) { vx = fmaxf(vx, 0.f); vy = fmaxf(vy, 0.f); }
                if (rs) {
                    vx += rs[(size_t)r1 * HD + colb];
                    vy += rs[(size_t)r1 * HD + colb + 1];
                }
                if (mode == 3) {
                    __nv_bfloat16 hx = __float2bfloat16(vx);
                    __nv_bfloat16 hy = __float2bfloat16(vy);
                    __nv_bfloat162 hh(hx, hy);
                    __nv_bfloat162 ll(
                        __float2bfloat16(vx - __bfloat162float(hx)),
                        __float2bfloat16(vy - __bfloat162float(hy)));
                    __nv_bfloat16* base = outAug + (size_t)r1 * 384;
                    *(uint32_t*)(base + colb)       = *(uint32_t*)&hh;
                    *(uint32_t*)(base + 128 + colb) = *(uint32_t*)&ll;
                    *(uint32_t*)(base + 256 + colb) = *(uint32_t*)&hh;
                } else {
                    *(float2*)(dst + (size_t)r1 * HD + colb) = make_float2(vx, vy);
                }
            }
        }
    }
}

// ---------------- CSR build (hierarchical scan) --------------------------------
__global__ void csr_zero(int* __restrict__ deg, int n) {
    int i = blockIdx.x * blockDim.x + threadIdx.x;
    if (i < n) deg[i] = 0;
}
__global__ void csr_count(const int* __restrict__ col, int* __restrict__ deg,
                          int nedges) {
    int i = blockIdx.x * blockDim.x + threadIdx.x;
    if (i < nedges) atomicAdd(deg + col[i], 1);
}
__global__ void __launch_bounds__(1024)
csr_scan1(const int* __restrict__ deg, int* __restrict__ off,
          int* __restrict__ part, int n)
{
    __shared__ int wsum[32];
    int t = threadIdx.x, lane = t & 31, w = t >> 5;
    int i = blockIdx.x * 1024 + t;
    int v = (i < n) ? deg[i] : 0;
    int x = v;
    #pragma unroll
    for (int o = 1; o < 32; o <<= 1) {
        int y = __shfl_up_sync(0xFFFFFFFFu, x, o);
        if (lane >= o) x += y;
    }
    if (lane == 31) wsum[w] = x;
    __syncthreads();
    if (w == 0) {
        int s = wsum[lane];
        #pragma unroll
        for (int o = 1; o < 32; o <<= 1) {
            int y = __shfl_up_sync(0xFFFFFFFFu, s, o);
            if (lane >= o) s += y;
        }
        wsum[lane] = s;
    }
    __syncthreads();
    int incl = x + (w > 0 ? wsum[w - 1] : 0);
    if (i < n) off[i] = incl - v;
    if (t == 1023) part[blockIdx.x] = incl;
}
__global__ void __launch_bounds__(64)
csr_scan2(int* __restrict__ part, int nb)
{
    __shared__ int w0;
    int t = threadIdx.x, lane = t & 31, w = t >> 5;
    int v = (t < nb) ? part[t] : 0;
    int x = v;
    #pragma unroll
    for (int o = 1; o < 32; o <<= 1) {
        int y = __shfl_up_sync(0xFFFFFFFFu, x, o);
        if (lane >= o) x += y;
    }
    if (w == 0 && lane == 31) w0 = x;
    __syncthreads();
    int incl = x + (w == 1 ? w0 : 0);
    if (t < nb) part[t] = incl - v;
    if (t == 63) part[nb] = incl;
}
__global__ void __launch_bounds__(1024)
csr_scan3(int* __restrict__ off, int* __restrict__ cur,
          const int* __restrict__ part, int n, int nb)
{
    int i = blockIdx.x * 1024 + threadIdx.x;
    if (i < n) {
        int o = off[i] + part[blockIdx.x];
        off[i] = o; cur[i] = o;
    }
    if (i == 0) off[n] = part[nb];
}
__global__ void csr_fill(const int* __restrict__ row, const int* __restrict__ col,
                         const float* __restrict__ dist,
                         int* __restrict__ cur, int* __restrict__ srow,
                         float* __restrict__ sdst, int nedges)
{
    int i = blockIdx.x * blockDim.x + threadIdx.x;
    if (i >= nedges) return;
    int pos = atomicAdd(cur + col[i], 1);
    srow[pos] = row[i];
    sdst[pos] = dist[i];
}

// ---------------- CSR edge aggregation ----------------------------------------
__global__ void __launch_bounds__(256)
edge_csr(const float* __restrict__ A, const float* __restrict__ B,
         const int* __restrict__ off, const int* __restrict__ srow,
         const float* __restrict__ sdst, const float* __restrict__ wd,
         __nv_bfloat16* __restrict__ gaug, int n)
{
    __shared__ __align__(16) float swd[HD];
    int t = threadIdx.x;
    if (t < HD) swd[t] = wd[t];
    __syncthreads();

    int lane = t & 31;
    int node = blockIdx.x * 8 + (t >> 5);
    if (node >= n) return;
    int f = lane * 4;

    float4 w = *(const float4*)(swd + f);
    float4 b = *(const float4*)(B + (size_t)node * HD + f);
    float4 acc = make_float4(0.f, 0.f, 0.f, 0.f);

    int s = __ldg(off + node), e = __ldg(off + node + 1);
    int i = s;
    for (; i + 1 < e; i += 2) {
        int   r0 = __ldg(srow + i),     r1 = __ldg(srow + i + 1);
        float d0 = __ldg(sdst + i),     d1 = __ldg(sdst + i + 1);
        float4 a0 = *(const float4*)(A + (size_t)r0 * HD + f);
        float4 a1 = *(const float4*)(A + (size_t)r1 * HD + f);
        acc.x += fmaxf(fmaf(d0, w.x, a0.x + b.x), 0.f) + fmaxf(fmaf(d1, w.x, a1.x + b.x), 0.f);
        acc.y += fmaxf(fmaf(d0, w.y, a0.y + b.y), 0.f) + fmaxf(fmaf(d1, w.y, a1.y + b.y), 0.f);
        acc.z += fmaxf(fmaf(d0, w.z, a0.z + b.z), 0.f) + fmaxf(fmaf(d1, w.z, a1.z + b.z), 0.f);
        acc.w += fmaxf(fmaf(d0, w.w, a0.w + b.w), 0.f) + fmaxf(fmaf(d1, w.w, a1.w + b.w), 0.f);
    }
    if (i < e) {
        int   r0 = __ldg(srow + i);
        float d0 = __ldg(sdst + i);
        float4 a0 = *(const float4*)(A + (size_t)r0 * HD + f);
        acc.x += fmaxf(fmaf(d0, w.x, a0.x + b.x), 0.f);
        acc.y += fmaxf(fmaf(d0, w.y, a0.y + b.y), 0.f);
        acc.z += fmaxf(fmaf(d0, w.z, a0.z + b.z), 0.f);
        acc.w += fmaxf(fmaf(d0, w.w, a0.w + b.w), 0.f);
    }

    __nv_bfloat16 h0 = __float2bfloat16(acc.x), h1 = __float2bfloat16(acc.y);
    __nv_bfloat16 h2 = __float2bfloat16(acc.z), h3 = __float2bfloat16(acc.w);
    __nv_bfloat162 hh0(h0, h1), hh1(h2, h3);
    __nv_bfloat162 ll0(__float2bfloat16(acc.x - __bfloat162float(h0)),
                       __float2bfloat16(acc.y - __bfloat162float(h1)));
    __nv_bfloat162 ll1(__float2bfloat16(acc.z - __bfloat162float(h2)),
                       __float2bfloat16(acc.w - __bfloat162float(h3)));
    uint2 hb = make_uint2(*(uint32_t*)&hh0, *(uint32_t*)&hh1);
    uint2 lb = make_uint2(*(uint32_t*)&ll0, *(uint32_t*)&ll1);
    __nv_bfloat16* base = gaug + (size_t)node * 384;
    *(uint2*)(base + f)       = hb;
    *(uint2*)(base + 128 + f) = lb;
    *(uint2*)(base + 256 + f) = hb;
}

// ---------------- weight prep: transpose + bf16 hi/lo, augmented layout -------
__global__ void prep_w(const float* __restrict__ wm1, const float* __restrict__ wm2,
                       const float* __restrict__ wr1, const float* __restrict__ wr2,
                       const float* __restrict__ wu1, const float* __restrict__ wu2)
{
    int slot = blockIdx.y;
    int idx = blockIdx.x * 256 + threadIdx.x;
    if (slot < 2) {
        if (idx >= 384 * 384) return;
        int n = idx / 384, k = idx % 384;
        int kb = k & 127, seg = k >> 7;
        const float* wm = slot ? wm2 : wm1;
        const float* wr = slot ? wr2 : wr1;
        float v;
        if (n < 128)       v = wm[kb * 128 + n];
        else if (n < 256)  v = wm[(128 + kb) * 128 + (n - 128)];
        else               v = wr[kb * 128 + (n - 256)];
        __nv_bfloat16 h = __float2bfloat16(v);
        g_wabr[slot][idx] = (seg == 2)
            ? __float2bfloat16(v - __bfloat162float(h)) : h;
    } else {
        if (idx >= 128 * 768) return;
        int n = idx / 768, k = idx % 768;
        int part = k / 384;
        int kb = k & 127, seg = (k % 384) >> 7;
        const float* wu = (slot == 3) ? wu2 : wu1;
        float v = wu[(part * 128 + kb) * 128 + n];
        __nv_bfloat16 h = __float2bfloat16(v);
        g_wupd[slot - 2][idx] = (seg == 2)
            ? __float2bfloat16(v - __bfloat162float(h)) : h;
    }
}

// ---------------- fp32 -> augmented bf16 [hi|lo|hi] ---------------------------
__global__ void conv_split(const float* __restrict__ in,
                           __nv_bfloat16* __restrict__ aug, int ntasks)
{
    int i = blockIdx.x * blockDim.x + threadIdx.x;
    int stride = gridDim.x * blockDim.x;
    for (; i < ntasks; i += stride) {
        int r = i >> 5;
        int c = (i & 31) * 4;
        float4 v = *(const float4*)(in + (size_t)r * HD + c);
        __nv_bfloat16 h0 = __float2bfloat16(v.x), h1 = __float2bfloat16(v.y);
        __nv_bfloat16 h2 = __float2bfloat16(v.z), h3 = __float2bfloat16(v.w);
        __nv_bfloat16 l0 = __float2bfloat16(v.x - __bfloat162float(h0));
        __nv_bfloat16 l1 = __float2bfloat16(v.y - __bfloat162float(h1));
        __nv_bfloat16 l2 = __float2bfloat16(v.z - __bfloat162float(h2));
        __nv_bfloat16 l3 = __float2bfloat16(v.w - __bfloat162float(h3));
        __nv_bfloat162 hh0(h0, h1), hh1(h2, h3), ll0(l0, l1), ll1(l2, l3);
        uint2 hbits = make_uint2(*(uint32_t*)&hh0, *(uint32_t*)&hh1);
        uint2 lbits = make_uint2(*(uint32_t*)&ll0, *(uint32_t*)&ll1);
        __nv_bfloat16* base = aug + (size_t)r * 384;
        *(uint2*)(base + c)       = hbits;
        *(uint2*)(base + 128 + c) = lbits;
        *(uint2*)(base + 256 + c) = hbits;
    }
}

// ---------------- zero kernel -------------------------------------------------
__global__ void zero_kernel(float* __restrict__ p, int n4) {
    int i = blockIdx.x * blockDim.x + threadIdx.x;
    int stride = gridDim.x * blockDim.x;
    float4 z = make_float4(0.f, 0.f, 0.f, 0.f);
    for (; i < n4; i += stride) ((float4*)p)[i] = z;
}

// ---------------- per-graph pooling ------------------------------------------
__global__ void __launch_bounds__(256)
pool_kernel(const float* __restrict__ h, const int* __restrict__ batch,
            float* __restrict__ pool, int n)
{
    int warp = (blockIdx.x * blockDim.x + threadIdx.x) >> 5;
    int lane = threadIdx.x & 31;
    if (warp >= n) return;
    int g = __ldg(batch + warp);
    float4 v = *(const float4*)(h + (size_t)warp * HD + lane * 4);
    red_add_v4(pool + (size_t)g * HD + lane * 4, v);
}

// ---------------- prediction head --------------------------------------------
__global__ void __launch_bounds__(128)
head_kernel(const float* __restrict__ pool,
            const float* __restrict__ wp1, const float* __restrict__ bp1,
            const float* __restrict__ wp2, const float* __restrict__ bp2,
            float* __restrict__ out)
{
    int b = blockIdx.x;
    int t = threadIdx.x;
    __shared__ float sg[HD];
    __shared__ float red[HD];

    sg[t] = pool[(size_t)b * HD + t];
    __syncthreads();

    float acc = bp1[t];
    #pragma unroll 8
    for (int k = 0; k < HD; k++)
        acc = fmaf(sg[k], wp1[(size_t)k * HD + t], acc);
    acc = fmaxf(acc, 0.f) * wp2[t];

    red[t] = acc;
    __syncthreads();
    for (int s = 64; s > 0; s >>= 1) {
        if (t < s) red[t] += red[t + s];
        __syncthreads();
    }
    if (t == 0) out[b] = red[0] + bp2[0];
}

// ---------------- host side ---------------------------------------------------
extern "C" void kernel_launch(void* const* d_in, const int* in_sizes, int n_in,
                              void* d_out, int out_size)
{
    const float* x      = (const float*)d_in[0];
    const float* edist  = (const float*)d_in[1];
    const int*   eidx   = (const int*)  d_in[2];
    const int*   batch  = (const int*)  d_in[3];
    const float* wres1  = (const float*)d_in[4];
    const float* wmsg1  = (const float*)d_in[5];
    const float* bmsg1  = (const float*)d_in[6];
    const float* wupd1  = (const float*)d_in[7];
    const float* bupd1  = (const float*)d_in[8];
    const float* wres2  = (const float*)d_in[9];
    const float* wmsg2  = (const float*)d_in[10];
    const float* bmsg2  = (const float*)d_in[11];
    const float* wupd2  = (const float*)d_in[12];
    const float* bupd2  = (const float*)d_in[13];
    const float* wp1    = (const float*)d_in[14];
    const float* bp1    = (const float*)d_in[15];
    const float* wp2    = (const float*)d_in[16];
    const float* bp2    = (const float*)d_in[17];
    float* out = (float*)d_out;

    int N = in_sizes[0] / HD;
    int E = in_sizes[1];
    int G = out_size;   // T == 1
    const int* erow = eidx;
    const int* ecol = eidx + E;

    float *A, *B, *R, *H2, *P;
    __nv_bfloat16 *XAUG, *GAUG, *WABR, *WUPD;
    int *DEG, *OFF, *CUR, *PART, *SROWP; float *SDST;
    cudaGetSymbolAddress((void**)&A,  g_A);
    cudaGetSymbolAddress((void**)&B,  g_Bv);
    cudaGetSymbolAddress((void**)&R,  g_R);
    cudaGetSymbolAddress((void**)&H2, g_h2);
    cudaGetSymbolAddress((void**)&P,  g_pool);
    cudaGetSymbolAddress((void**)&XAUG, g_xaug);
    cudaGetSymbolAddress((void**)&GAUG, g_gaug);
    cudaGetSymbolAddress((void**)&WABR, g_wabr);
    cudaGetSymbolAddress((void**)&WUPD, g_wupd);
    cudaGetSymbolAddress((void**)&DEG, g_deg);
    cudaGetSymbolAddress((void**)&OFF, g_off);
    cudaGetSymbolAddress((void**)&CUR, g_cur);
    cudaGetSymbolAddress((void**)&PART, g_part);
    cudaGetSymbolAddress((void**)&SROWP, g_srow);
    cudaGetSymbolAddress((void**)&SDST, g_sdst);
    __nv_bfloat16* WABR1 = WABR + (size_t)384 * 384;
    __nv_bfloat16* WUPD1 = WUPD + (size_t)128 * 768;

    cudaFuncSetAttribute((const void*)bmma_gemm,
                         cudaFuncAttributeMaxDynamicSharedMemorySize, GEMM_SMEM);

    int nblk = (N + BM - 1) / BM;
    int node_blocks = (N + 7) / 8;
    int nscan = (N + 1023) / 1024;

    // weight prep + CSR build (edge structure shared by both layers)
    {
        dim3 gp(576, 4);
        prep_w<<<gp, 256>>>(wmsg1, wmsg2, wres1, wres2, wupd1, wupd2);
    }
    csr_zero<<<(N + 255) / 256, 256>>>(DEG, N);
    csr_count<<<(E + 255) / 256, 256>>>(ecol, DEG, E);
    csr_scan1<<<nscan, 1024>>>(DEG, OFF, PART, N);
    csr_scan2<<<1, 64>>>(PART, nscan);
    csr_scan3<<<nscan, 1024>>>(OFF, CUR, PART, N, nscan);
    csr_fill<<<(E + 255) / 256, 256>>>(erow, ecol, edist, CUR, SROWP, SDST, E);

    dim3 gabr(nblk, 3), g1(nblk, 1);

    // ---------- layer 1 ----------
    conv_split<<<1024, 256>>>(x, XAUG, N * 32);
    bmma_gemm<<<gabr, 256, GEMM_SMEM>>>(XAUG, nullptr, WABR, 384, bmsg1, nullptr,
                                        A, B, R, nullptr, N, 1);
    edge_csr<<<node_blocks, 256>>>(A, B, OFF, SROWP, SDST, wmsg1 + 256 * HD, GAUG, N);
    // UPD-1: writes layer-2 XAUG directly (in-place safe: block-local rows)
    bmma_gemm<<<g1, 256, GEMM_SMEM>>>(XAUG, GAUG, WUPD, 768, bupd1, R,
                                      nullptr, nullptr, nullptr, XAUG, N, 3);

    // ---------- layer 2 ----------
    bmma_gemm<<<gabr, 256, GEMM_SMEM>>>(XAUG, nullptr, WABR1, 384, bmsg2, nullptr,
                                        A, B, R, nullptr, N, 1);
    edge_csr<<<node_blocks, 256>>>(A, B, OFF, SROWP, SDST, wmsg2 + 256 * HD, GAUG, N);
    bmma_gemm<<<g1, 256, GEMM_SMEM>>>(XAUG, GAUG, WUPD1, 768, bupd2, R,
                                      H2, nullptr, nullptr, nullptr, N, 2);

    // ---------- pooling + head ----------
    zero_kernel<<<4, 256>>>(P, (G * HD) / 4);
    int pool_blocks = (N * 32 + 255) / 256;
    pool_kernel<<<pool_blocks, 256>>>(H2, batch, P, N);
    head_kernel<<<G, 128>>>(P, wp1, bp1, wp2, bp2, out);
}

// round 13
// speedup vs baseline: 1.2057x; 1.2057x over previous
#include <cuda_runtime.h>
#include <cuda_bf16.h>
#include <cstdint>

#define HD 128
#define MAXN 50000
#define MAXE 800000
#define MAXG 64

// ---------------- scratch (static __device__ arrays; no allocation) ----------
__device__ __align__(16) float g_A   [(size_t)MAXN * HD];
__device__ __align__(16) float g_Bv  [(size_t)MAXN * HD];
__device__ __align__(16) float g_R   [(size_t)MAXN * HD];
__device__ __align__(16) float g_h2  [(size_t)MAXN * HD];
__device__ __align__(16) float g_pool[(size_t)MAXG * HD];
// augmented bf16 activations: [n, 384] = [hi(128) | lo(128) | hi(128)]
__device__ __align__(16) __nv_bfloat16 g_xaug[(size_t)MAXN * 384];
__device__ __align__(16) __nv_bfloat16 g_gaug[(size_t)MAXN * 384];
// augmented weights, [n, k'] row-major
__device__ __align__(16) __nv_bfloat16 g_wabr[2][384 * 384];
__device__ __align__(16) __nv_bfloat16 g_wupd[2][128 * 768];
// CSR scratch
__device__ int   g_deg [MAXN];
__device__ int   g_off [MAXN + 1];
__device__ int   g_cur [MAXN];
__device__ int   g_part[80];
__device__ int   g_srow[MAXE];
__device__ float g_sdst[MAXE];

// ---------------- helpers ----------------------------------------------------
__device__ __forceinline__ void red_add_v4(float* dst, float4 v) {
    asm volatile("red.global.add.v4.f32 [%0], {%1,%2,%3,%4};"
                 :: "l"(dst), "f"(v.x), "f"(v.y), "f"(v.z), "f"(v.w) : "memory");
}
__device__ __forceinline__ uint32_t smem_u32(const void* p) {
    uint32_t a;
    asm("{ .reg .u64 t; cvta.to.shared.u64 t, %1; cvt.u32.u64 %0, t; }"
        : "=r"(a) : "l"(p));
    return a;
}
__device__ __forceinline__ void cp_async16(uint32_t dst, const void* src) {
    asm volatile("cp.async.ca.shared.global [%0], [%1], 16;"
                 :: "r"(dst), "l"(src) : "memory");
}
__device__ __forceinline__ void cp_commit() {
    asm volatile("cp.async.commit_group;" ::: "memory");
}
template <int N>
__device__ __forceinline__ void cp_wait() {
    asm volatile("cp.async.wait_group %0;" :: "n"(N) : "memory");
}
__device__ __forceinline__ void ldmatrix_x4(uint32_t* r, uint32_t addr) {
    asm volatile("ldmatrix.sync.aligned.m8n8.x4.shared.b16 {%0,%1,%2,%3}, [%4];"
                 : "=r"(r[0]), "=r"(r[1]), "=r"(r[2]), "=r"(r[3]) : "r"(addr));
}
__device__ __forceinline__ void mma16816(float* d, const uint32_t* a,
                                         uint32_t b0, uint32_t b1) {
    asm volatile("mma.sync.aligned.m16n8k16.row.col.f32.bf16.bf16.f32 "
                 "{%0,%1,%2,%3}, {%4,%5,%6,%7}, {%8,%9}, {%0,%1,%2,%3};"
                 : "+f"(d[0]), "+f"(d[1]), "+f"(d[2]), "+f"(d[3])
                 : "r"(a[0]), "r"(a[1]), "r"(a[2]), "r"(a[3]),
                   "r"(b0), "r"(b1));
}

// ---------------- bf16 tensor-core GEMM (3-stage, measured-best) --------------
// 128x128 tile, 8 warps (4m x 2n), warp tile 32x64, BK=32, ldmatrix frags.
// mode 1 (ABR): K'=384, grid.y: 0->outA, 1->outB(+bias), 2->outR
// mode 2 (UPD): K'=768, out fp32 = resid + relu(acc + bias)
// mode 3 (UPD): same math, write augmented bf16 [hi|lo|hi] to outAug
#define SROW 40
#define SBUFB (128 * SROW * 2)          // 10240 bytes per stage per operand
#define STAGES 3
#define GEMM_SMEM (STAGES * SBUFB * 2)  // 61440 bytes

__device__ __forceinline__ void stage_load(
    int s, int t, int row0, int nrows,
    const __nv_bfloat16* __restrict__ A0, const __nv_bfloat16* __restrict__ A1,
    const __nv_bfloat16* __restrict__ Wp, int wstride,
    uint32_t smbase)
{
    int buf = s % STAGES;
    int kk = (s % 12) * 32;
    int koff = (s / 12) * 384 + kk;
    const __nv_bfloat16* Asrc = (s < 12) ? A0 : A1;
    uint32_t dA = smbase + (uint32_t)buf * SBUFB;
    uint32_t dB = smbase + (uint32_t)(STAGES * SBUFB) + (uint32_t)buf * SBUFB;
    #pragma unroll
    for (int i = t * 2; i < t * 2 + 2; i++) {
        int r = i >> 2, q = i & 3;              // 128 rows x 4 quads
        int gr = row0 + r; if (gr >= nrows) gr = nrows - 1;
        cp_async16(dA + r * 80 + q * 16, Asrc + (size_t)gr * 384 + kk + q * 8);
        cp_async16(dB + r * 80 + q * 16, Wp + (size_t)r * wstride + koff + q * 8);
    }
    cp_commit();
}

__global__ void __launch_bounds__(256)
bmma_gemm(const __nv_bfloat16* __restrict__ A0,
          const __nv_bfloat16* __restrict__ A1,
          const __nv_bfloat16* __restrict__ W, int wstride,
          const float* __restrict__ bias, const float* __restrict__ resid,
          float* __restrict__ outA, float* __restrict__ outB,
          float* __restrict__ outR, __nv_bfloat16* __restrict__ outAug,
          int nrows, int mode)
{
    extern __shared__ char smraw[];
    uint32_t smbase = smem_u32(smraw);

    int t = threadIdx.x;
    int warp = t >> 5, lane = t & 31;
    int wm = warp & 3, wn = warp >> 2;       // 4 x 2 warp grid
    int g = lane >> 2, tg = lane & 3;
    int row0 = blockIdx.x * 128;
    const __nv_bfloat16* Wp = W + (size_t)(blockIdx.y * 128) * wstride;

    int nsteps = (mode >= 2) ? 24 : 12;

    float acc[2][8][4];
    #pragma unroll
    for (int i = 0; i < 2; i++)
        #pragma unroll
        for (int j = 0; j < 8; j++)
            #pragma unroll
            for (int k = 0; k < 4; k++) acc[i][j][k] = 0.f;

    uint32_t aLane = (uint32_t)(((lane & 15) * SROW + (lane >> 4) * 8) * 2);
    uint32_t bLane = (uint32_t)((((lane >> 4) * 8 + (lane & 7)) * SROW
                               + ((lane >> 3) & 1) * 8) * 2);

    stage_load(0, t, row0, nrows, A0, A1, Wp, wstride, smbase);
    stage_load(1, t, row0, nrows, A0, A1, Wp, wstride, smbase);

    for (int s = 0; s < nsteps; ++s) {
        cp_wait<1>();
        __syncthreads();
        if (s + 2 < nsteps)
            stage_load(s + 2, t, row0, nrows, A0, A1, Wp, wstride, smbase);
        else
            cp_commit();   // empty group keeps wait<1> semantics uniform

        int buf = s % STAGES;
        uint32_t bufA = smbase + (uint32_t)buf * SBUFB;
        uint32_t bufB = smbase + (uint32_t)(STAGES * SBUFB) + (uint32_t)buf * SBUFB;

        #pragma unroll
        for (int ks = 0; ks < 32; ks += 16) {
            uint32_t aF[2][4];
            #pragma unroll
            for (int mi = 0; mi < 2; mi++)
                ldmatrix_x4(aF[mi],
                    bufA + (uint32_t)(((wm * 32 + mi * 16) * SROW + ks) * 2) + aLane);
            uint32_t bF[8][2];
            #pragma unroll
            for (int p = 0; p < 4; p++) {
                uint32_t r[4];
                ldmatrix_x4(r,
                    bufB + (uint32_t)(((wn * 64 + p * 16) * SROW + ks) * 2) + bLane);
                bF[2 * p][0] = r[0]; bF[2 * p][1] = r[1];
                bF[2 * p + 1][0] = r[2]; bF[2 * p + 1][1] = r[3];
            }
            #pragma unroll
            for (int ni = 0; ni < 8; ni++) {
                mma16816(acc[0][ni], aF[0], bF[ni][0], bF[ni][1]);
                mma16816(acc[1][ni], aF[1], bF[ni][0], bF[ni][1]);
            }
        }
        __syncthreads();
    }

    // ---- epilogue ----
    float* dst = outA;
    const float* bi = nullptr;
    const float* rs = nullptr;
    bool dorelu = false;
    if (mode == 1) {
        if (blockIdx.y == 0)      dst = outA;
        else if (blockIdx.y == 1) { dst = outB; bi = bias; }
        else                      dst = outR;
    } else {
        bi = bias; rs = resid; dorelu = true;
    }

    #pragma unroll
    for (int mi = 0; mi < 2; mi++) {
        #pragma unroll
        for (int ni = 0; ni < 8; ni++) {
            int colb = wn * 64 + ni * 8 + tg * 2;
            float bx = 0.f, by = 0.f;
            if (bi) { bx = __ldg(bi + colb); by = __ldg(bi + colb + 1); }
            #pragma unroll
            for (int h = 0; h < 2; h++) {
                int r1 = row0 + wm * 32 + mi * 16 + g + h * 8;
                if (r1 >= nrows) continue;
                float vx = acc[mi][ni][2 * h]     + bx;
                float vy = acc[mi][ni][2 * h + 1] + by;
                if (dorelu) { vx = fmaxf(vx, 0.f); vy = fmaxf(vy, 0.f); }
                if (rs) {
                    vx += rs[(size_t)r1 * HD + colb];
                    vy += rs[(size_t)r1 * HD + colb + 1];
                }
                if (mode == 3) {
                    __nv_bfloat16 hx = __float2bfloat16(vx);
                    __nv_bfloat16 hy = __float2bfloat16(vy);
                    __nv_bfloat162 hh(hx, hy);
                    __nv_bfloat162 ll(
                        __float2bfloat16(vx - __bfloat162float(hx)),
                        __float2bfloat16(vy - __bfloat162float(hy)));
                    __nv_bfloat16* base = outAug + (size_t)r1 * 384;
                    *(uint32_t*)(base + colb)       = *(uint32_t*)&hh;
                    *(uint32_t*)(base + 128 + colb) = *(uint32_t*)&ll;
                    *(uint32_t*)(base + 256 + colb) = *(uint32_t*)&hh;
                } else {
                    *(float2*)(dst + (size_t)r1 * HD + colb) = make_float2(vx, vy);
                }
            }
        }
    }
}

// ---------------- CSR build (hierarchical scan) --------------------------------
__global__ void csr_zero(int* __restrict__ deg, int n) {
    int i = blockIdx.x * blockDim.x + threadIdx.x;
    if (i < n) deg[i] = 0;
}
__global__ void csr_count(const int* __restrict__ col, int* __restrict__ deg,
                          int nedges) {
    int i = blockIdx.x * blockDim.x + threadIdx.x;
    if (i < nedges) atomicAdd(deg + col[i], 1);
}
// phase 1: block-local exclusive scan; per-block total -> part[blockIdx]
__global__ void __launch_bounds__(1024)
csr_scan1(const int* __restrict__ deg, int* __restrict__ off,
          int* __restrict__ part, int n)
{
    __shared__ int wsum[32];
    int t = threadIdx.x, lane = t & 31, w = t >> 5;
    int i = blockIdx.x * 1024 + t;
    int v = (i < n) ? deg[i] : 0;
    int x = v;
    #pragma unroll
    for (int o = 1; o < 32; o <<= 1) {
        int y = __shfl_up_sync(0xFFFFFFFFu, x, o);
        if (lane >= o) x += y;
    }
    if (lane == 31) wsum[w] = x;
    __syncthreads();
    if (w == 0) {
        int s = wsum[lane];
        #pragma unroll
        for (int o = 1; o < 32; o <<= 1) {
            int y = __shfl_up_sync(0xFFFFFFFFu, s, o);
            if (lane >= o) s += y;
        }
        wsum[lane] = s;
    }
    __syncthreads();
    int incl = x + (w > 0 ? wsum[w - 1] : 0);
    if (i < n) off[i] = incl - v;
    if (t == 1023) part[blockIdx.x] = incl;
}
// phase 2: exclusive-scan the <=64 block totals; part[nb] = grand total
__global__ void __launch_bounds__(64)
csr_scan2(int* __restrict__ part, int nb)
{
    __shared__ int w0;
    int t = threadIdx.x, lane = t & 31, w = t >> 5;
    int v = (t < nb) ? part[t] : 0;
    int x = v;
    #pragma unroll
    for (int o = 1; o < 32; o <<= 1) {
        int y = __shfl_up_sync(0xFFFFFFFFu, x, o);
        if (lane >= o) x += y;
    }
    if (w == 0 && lane == 31) w0 = x;
    __syncthreads();
    int incl = x + (w == 1 ? w0 : 0);
    if (t < nb) part[t] = incl - v;
    if (t == 63) part[nb] = incl;
}
// phase 3: add block offsets, produce off/cur and off[n]
__global__ void __launch_bounds__(1024)
csr_scan3(int* __restrict__ off, int* __restrict__ cur,
          const int* __restrict__ part, int n, int nb)
{
    int i = blockIdx.x * 1024 + threadIdx.x;
    if (i < n) {
        int o = off[i] + part[blockIdx.x];
        off[i] = o; cur[i] = o;
    }
    if (i == 0) off[n] = part[nb];
}
__global__ void csr_fill(const int* __restrict__ row, const int* __restrict__ col,
                         const float* __restrict__ dist,
                         int* __restrict__ cur, int* __restrict__ srow,
                         float* __restrict__ sdst, int nedges)
{
    int i = blockIdx.x * blockDim.x + threadIdx.x;
    if (i >= nedges) return;
    int pos = atomicAdd(cur + col[i], 1);
    srow[pos] = row[i];
    sdst[pos] = dist[i];
}

// ---------------- CSR edge aggregation ----------------------------------------
// warp per destination node: aggr = sum over in-edges of relu(A[row]+B'[n]+d*w)
// writes augmented bf16 [hi|lo|hi] directly.
__global__ void __launch_bounds__(256)
edge_csr(const float* __restrict__ A, const float* __restrict__ B,
         const int* __restrict__ off, const int* __restrict__ srow,
         const float* __restrict__ sdst, const float* __restrict__ wd,
         __nv_bfloat16* __restrict__ gaug, int n)
{
    __shared__ __align__(16) float swd[HD];
    int t = threadIdx.x;
    if (t < HD) swd[t] = wd[t];
    __syncthreads();

    int lane = t & 31;
    int node = blockIdx.x * 8 + (t >> 5);
    if (node >= n) return;
    int f = lane * 4;

    float4 w = *(const float4*)(swd + f);
    float4 b = *(const float4*)(B + (size_t)node * HD + f);
    float4 acc = make_float4(0.f, 0.f, 0.f, 0.f);

    int s = __ldg(off + node), e = __ldg(off + node + 1);
    int i = s;
    for (; i + 1 < e; i += 2) {
        int   r0 = __ldg(srow + i),     r1 = __ldg(srow + i + 1);
        float d0 = __ldg(sdst + i),     d1 = __ldg(sdst + i + 1);
        float4 a0 = *(const float4*)(A + (size_t)r0 * HD + f);
        float4 a1 = *(const float4*)(A + (size_t)r1 * HD + f);
        acc.x += fmaxf(fmaf(d0, w.x, a0.x + b.x), 0.f) + fmaxf(fmaf(d1, w.x, a1.x + b.x), 0.f);
        acc.y += fmaxf(fmaf(d0, w.y, a0.y + b.y), 0.f) + fmaxf(fmaf(d1, w.y, a1.y + b.y), 0.f);
        acc.z += fmaxf(fmaf(d0, w.z, a0.z + b.z), 0.f) + fmaxf(fmaf(d1, w.z, a1.z + b.z), 0.f);
        acc.w += fmaxf(fmaf(d0, w.w, a0.w + b.w), 0.f) + fmaxf(fmaf(d1, w.w, a1.w + b.w), 0.f);
    }
    if (i < e) {
        int   r0 = __ldg(srow + i);
        float d0 = __ldg(sdst + i);
        float4 a0 = *(const float4*)(A + (size_t)r0 * HD + f);
        acc.x += fmaxf(fmaf(d0, w.x, a0.x + b.x), 0.f);
        acc.y += fmaxf(fmaf(d0, w.y, a0.y + b.y), 0.f);
        acc.z += fmaxf(fmaf(d0, w.z, a0.z + b.z), 0.f);
        acc.w += fmaxf(fmaf(d0, w.w, a0.w + b.w), 0.f);
    }

    __nv_bfloat16 h0 = __float2bfloat16(acc.x), h1 = __float2bfloat16(acc.y);
    __nv_bfloat16 h2 = __float2bfloat16(acc.z), h3 = __float2bfloat16(acc.w);
    __nv_bfloat162 hh0(h0, h1), hh1(h2, h3);
    __nv_bfloat162 ll0(__float2bfloat16(acc.x - __bfloat162float(h0)),
                       __float2bfloat16(acc.y - __bfloat162float(h1)));
    __nv_bfloat162 ll1(__float2bfloat16(acc.z - __bfloat162float(h2)),
                       __float2bfloat16(acc.w - __bfloat162float(h3)));
    uint2 hb = make_uint2(*(uint32_t*)&hh0, *(uint32_t*)&hh1);
    uint2 lb = make_uint2(*(uint32_t*)&ll0, *(uint32_t*)&ll1);
    __nv_bfloat16* base = gaug + (size_t)node * 384;
    *(uint2*)(base + f)       = hb;
    *(uint2*)(base + 128 + f) = lb;
    *(uint2*)(base + 256 + f) = hb;
}

// ---------------- weight prep: transpose + bf16 hi/lo, augmented layout -------
__global__ void prep_w(const float* __restrict__ wm1, const float* __restrict__ wm2,
                       const float* __restrict__ wr1, const float* __restrict__ wr2,
                       const float* __restrict__ wu1, const float* __restrict__ wu2)
{
    int slot = blockIdx.y;
    int idx = blockIdx.x * 256 + threadIdx.x;
    if (slot < 2) {
        if (idx >= 384 * 384) return;
        int n = idx / 384, k = idx % 384;
        int kb = k & 127, seg = k >> 7;
        const float* wm = slot ? wm2 : wm1;
        const float* wr = slot ? wr2 : wr1;
        float v;
        if (n < 128)       v = wm[kb * 128 + n];
        else if (n < 256)  v = wm[(128 + kb) * 128 + (n - 128)];
        else               v = wr[kb * 128 + (n - 256)];
        __nv_bfloat16 h = __float2bfloat16(v);
        g_wabr[slot][idx] = (seg == 2)
            ? __float2bfloat16(v - __bfloat162float(h)) : h;
    } else {
        if (idx >= 128 * 768) return;
        int n = idx / 768, k = idx % 768;
        int part = k / 384;
        int kb = k & 127, seg = (k % 384) >> 7;
        const float* wu = (slot == 3) ? wu2 : wu1;
        float v = wu[(part * 128 + kb) * 128 + n];
        __nv_bfloat16 h = __float2bfloat16(v);
        g_wupd[slot - 2][idx] = (seg == 2)
            ? __float2bfloat16(v - __bfloat162float(h)) : h;
    }
}

// ---------------- fp32 -> augmented bf16 [hi|lo|hi] ---------------------------
__global__ void conv_split(const float* __restrict__ in,
                           __nv_bfloat16* __restrict__ aug, int ntasks)
{
    int i = blockIdx.x * blockDim.x + threadIdx.x;
    int stride = gridDim.x * blockDim.x;
    for (; i < ntasks; i += stride) {
        int r = i >> 5;
        int c = (i & 31) * 4;
        float4 v = *(const float4*)(in + (size_t)r * HD + c);
        __nv_bfloat16 h0 = __float2bfloat16(v.x), h1 = __float2bfloat16(v.y);
        __nv_bfloat16 h2 = __float2bfloat16(v.z), h3 = __float2bfloat16(v.w);
        __nv_bfloat16 l0 = __float2bfloat16(v.x - __bfloat162float(h0));
        __nv_bfloat16 l1 = __float2bfloat16(v.y - __bfloat162float(h1));
        __nv_bfloat16 l2 = __float2bfloat16(v.z - __bfloat162float(h2));
        __nv_bfloat16 l3 = __float2bfloat16(v.w - __bfloat162float(h3));
        __nv_bfloat162 hh0(h0, h1), hh1(h2, h3), ll0(l0, l1), ll1(l2, l3);
        uint2 hbits = make_uint2(*(uint32_t*)&hh0, *(uint32_t*)&hh1);
        uint2 lbits = make_uint2(*(uint32_t*)&ll0, *(uint32_t*)&ll1);
        __nv_bfloat16* base = aug + (size_t)r * 384;
        *(uint2*)(base + c)       = hbits;
        *(uint2*)(base + 128 + c) = lbits;
        *(uint2*)(base + 256 + c) = hbits;
    }
}

// ---------------- zero kernel -------------------------------------------------
__global__ void zero_kernel(float* __restrict__ p, int n4) {
    int i = blockIdx.x * blockDim.x + threadIdx.x;
    int stride = gridDim.x * blockDim.x;
    float4 z = make_float4(0.f, 0.f, 0.f, 0.f);
    for (; i < n4; i += stride) ((float4*)p)[i] = z;
}

// ---------------- per-graph pooling ------------------------------------------
__global__ void __launch_bounds__(256)
pool_kernel(const float* __restrict__ h, const int* __restrict__ batch,
            float* __restrict__ pool, int n)
{
    int warp = (blockIdx.x * blockDim.x + threadIdx.x) >> 5;
    int lane = threadIdx.x & 31;
    if (warp >= n) return;
    int g = __ldg(batch + warp);
    float4 v = *(const float4*)(h + (size_t)warp * HD + lane * 4);
    red_add_v4(pool + (size_t)g * HD + lane * 4, v);
}

// ---------------- prediction head --------------------------------------------
__global__ void __launch_bounds__(128)
head_kernel(const float* __restrict__ pool,
            const float* __restrict__ wp1, const float* __restrict__ bp1,
            const float* __restrict__ wp2, const float* __restrict__ bp2,
            float* __restrict__ out)
{
    int b = blockIdx.x;
    int t = threadIdx.x;
    __shared__ float sg[HD];
    __shared__ float red[HD];

    sg[t] = pool[(size_t)b * HD + t];
    __syncthreads();

    float acc = bp1[t];
    #pragma unroll 8
    for (int k = 0; k < HD; k++)
        acc = fmaf(sg[k], wp1[(size_t)k * HD + t], acc);
    acc = fmaxf(acc, 0.f) * wp2[t];

    red[t] = acc;
    __syncthreads();
    for (int s = 64; s > 0; s >>= 1) {
        if (t < s) red[t] += red[t + s];
        __syncthreads();
    }
    if (t == 0) out[b] = red[0] + bp2[0];
}

// ---------------- host side ---------------------------------------------------
extern "C" void kernel_launch(void* const* d_in, const int* in_sizes, int n_in,
                              void* d_out, int out_size)
{
    const float* x      = (const float*)d_in[0];
    const float* edist  = (const float*)d_in[1];
    const int*   eidx   = (const int*)  d_in[2];
    const int*   batch  = (const int*)  d_in[3];
    const float* wres1  = (const float*)d_in[4];
    const float* wmsg1  = (const float*)d_in[5];
    const float* bmsg1  = (const float*)d_in[6];
    const float* wupd1  = (const float*)d_in[7];
    const float* bupd1  = (const float*)d_in[8];
    const float* wres2  = (const float*)d_in[9];
    const float* wmsg2  = (const float*)d_in[10];
    const float* bmsg2  = (const float*)d_in[11];
    const float* wupd2  = (const float*)d_in[12];
    const float* bupd2  = (const float*)d_in[13];
    const float* wp1    = (const float*)d_in[14];
    const float* bp1    = (const float*)d_in[15];
    const float* wp2    = (const float*)d_in[16];
    const float* bp2    = (const float*)d_in[17];
    float* out = (float*)d_out;

    int N = in_sizes[0] / HD;
    int E = in_sizes[1];
    int G = out_size;   // T == 1
    const int* erow = eidx;
    const int* ecol = eidx + E;

    float *A, *B, *R, *H2, *P;
    __nv_bfloat16 *XAUG, *GAUG, *WABR, *WUPD;
    int *DEG, *OFF, *CUR, *PART, *SROWP; float *SDST;
    cudaGetSymbolAddress((void**)&A,  g_A);
    cudaGetSymbolAddress((void**)&B,  g_Bv);
    cudaGetSymbolAddress((void**)&R,  g_R);
    cudaGetSymbolAddress((void**)&H2, g_h2);
    cudaGetSymbolAddress((void**)&P,  g_pool);
    cudaGetSymbolAddress((void**)&XAUG, g_xaug);
    cudaGetSymbolAddress((void**)&GAUG, g_gaug);
    cudaGetSymbolAddress((void**)&WABR, g_wabr);
    cudaGetSymbolAddress((void**)&WUPD, g_wupd);
    cudaGetSymbolAddress((void**)&DEG, g_deg);
    cudaGetSymbolAddress((void**)&OFF, g_off);
    cudaGetSymbolAddress((void**)&CUR, g_cur);
    cudaGetSymbolAddress((void**)&PART, g_part);
    cudaGetSymbolAddress((void**)&SROWP, g_srow);
    cudaGetSymbolAddress((void**)&SDST, g_sdst);
    __nv_bfloat16* WABR1 = WABR + (size_t)384 * 384;
    __nv_bfloat16* WUPD1 = WUPD + (size_t)128 * 768;

    cudaFuncSetAttribute((const void*)bmma_gemm,
                         cudaFuncAttributeMaxDynamicSharedMemorySize, GEMM_SMEM);

    int nblk = (N + 127) / 128;
    int node_blocks = (N + 7) / 8;
    int nscan = (N + 1023) / 1024;          // <= 64 blocks for N <= 65536

    // weight prep + CSR build (edge structure shared by both layers)
    {
        dim3 gp(576, 4);
        prep_w<<<gp, 256>>>(wmsg1, wmsg2, wres1, wres2, wupd1, wupd2);
    }
    csr_zero<<<(N + 255) / 256, 256>>>(DEG, N);
    csr_count<<<(E + 255) / 256, 256>>>(ecol, DEG, E);
    csr_scan1<<<nscan, 1024>>>(DEG, OFF, PART, N);
    csr_scan2<<<1, 64>>>(PART, nscan);
    csr_scan3<<<nscan, 1024>>>(OFF, CUR, PART, N, nscan);
    csr_fill<<<(E + 255) / 256, 256>>>(erow, ecol, edist, CUR, SROWP, SDST, E);

    dim3 gabr(nblk, 3), g1(nblk, 1);

    // ---------- layer 1 ----------
    conv_split<<<1024, 256>>>(x, XAUG, N * 32);
    bmma_gemm<<<gabr, 256, GEMM_SMEM>>>(XAUG, nullptr, WABR, 384, bmsg1, nullptr,
                                        A, B, R, nullptr, N, 1);
    edge_csr<<<node_blocks, 256>>>(A, B, OFF, SROWP, SDST, wmsg1 + 256 * HD, GAUG, N);
    // UPD-1: writes layer-2 XAUG directly (in-place safe: block-local rows)
    bmma_gemm<<<g1, 256, GEMM_SMEM>>>(XAUG, GAUG, WUPD, 768, bupd1, R,
                                      nullptr, nullptr, nullptr, XAUG, N, 3);

    // ---------- layer 2 ----------
    bmma_gemm<<<gabr, 256, GEMM_SMEM>>>(XAUG, nullptr, WABR1, 384, bmsg2, nullptr,
                                        A, B, R, nullptr, N, 1);
    edge_csr<<<node_blocks, 256>>>(A, B, OFF, SROWP, SDST, wmsg2 + 256 * HD, GAUG, N);
    bmma_gemm<<<g1, 256, GEMM_SMEM>>>(XAUG, GAUG, WUPD1, 768, bupd2, R,
                                      H2, nullptr, nullptr, nullptr, N, 2);

    // ---------- pooling + head ----------
    zero_kernel<<<4, 256>>>(P, (G * HD) / 4);
    int pool_blocks = (N * 32 + 255) / 256;
    pool_kernel<<<pool_blocks, 256>>>(H2, batch, P, N);
    head_kernel<<<G, 128>>>(P, wp1, bp1, wp2, bp2, out);
}

// round 14
// speedup vs baseline: 1.2375x; 1.0264x over previous
#include <cuda_runtime.h>
#include <cuda_bf16.h>
#include <cstdint>

#define HD 128
#define MAXN 50000
#define MAXE 800000
#define MAXG 64

// ---------------- scratch (static __device__ arrays; no allocation) ----------
__device__ __align__(16) float g_A   [(size_t)MAXN * HD];
__device__ __align__(16) float g_Bv  [(size_t)MAXN * HD];
__device__ __align__(16) float g_R   [(size_t)MAXN * HD];
__device__ __align__(16) float g_pool[(size_t)MAXG * HD];
// augmented bf16 activations: [n, 384] = [hi(128) | lo(128) | hi(128)]
__device__ __align__(16) __nv_bfloat16 g_xaug[(size_t)MAXN * 384];
__device__ __align__(16) __nv_bfloat16 g_gaug[(size_t)MAXN * 384];
// augmented weights, [n, k'] row-major
__device__ __align__(16) __nv_bfloat16 g_wabr[2][384 * 384];
__device__ __align__(16) __nv_bfloat16 g_wupd[2][128 * 768];
// CSR scratch
__device__ int   g_deg [MAXN];
__device__ int   g_off [MAXN + 1];
__device__ int   g_cur [MAXN];
__device__ int   g_part[80];
__device__ int   g_srow[MAXE];
__device__ float g_sdst[MAXE];

// ---------------- helpers ----------------------------------------------------
__device__ __forceinline__ void red_add_v2(float* dst, float x, float y) {
    asm volatile("red.global.add.v2.f32 [%0], {%1,%2};"
                 :: "l"(dst), "f"(x), "f"(y) : "memory");
}
__device__ __forceinline__ uint32_t smem_u32(const void* p) {
    uint32_t a;
    asm("{ .reg .u64 t; cvta.to.shared.u64 t, %1; cvt.u32.u64 %0, t; }"
        : "=r"(a) : "l"(p));
    return a;
}
__device__ __forceinline__ void cp_async16(uint32_t dst, const void* src) {
    asm volatile("cp.async.ca.shared.global [%0], [%1], 16;"
                 :: "r"(dst), "l"(src) : "memory");
}
__device__ __forceinline__ void cp_commit() {
    asm volatile("cp.async.commit_group;" ::: "memory");
}
template <int N>
__device__ __forceinline__ void cp_wait() {
    asm volatile("cp.async.wait_group %0;" :: "n"(N) : "memory");
}
__device__ __forceinline__ void ldmatrix_x4(uint32_t* r, uint32_t addr) {
    asm volatile("ldmatrix.sync.aligned.m8n8.x4.shared.b16 {%0,%1,%2,%3}, [%4];"
                 : "=r"(r[0]), "=r"(r[1]), "=r"(r[2]), "=r"(r[3]) : "r"(addr));
}
__device__ __forceinline__ void mma16816(float* d, const uint32_t* a,
                                         uint32_t b0, uint32_t b1) {
    asm volatile("mma.sync.aligned.m16n8k16.row.col.f32.bf16.bf16.f32 "
                 "{%0,%1,%2,%3}, {%4,%5,%6,%7}, {%8,%9}, {%0,%1,%2,%3};"
                 : "+f"(d[0]), "+f"(d[1]), "+f"(d[2]), "+f"(d[3])
                 : "r"(a[0]), "r"(a[1]), "r"(a[2]), "r"(a[3]),
                   "r"(b0), "r"(b1));
}

// ---------------- bf16 tensor-core GEMM (3-stage, measured-best) --------------
// 128x128 tile, 8 warps (4m x 2n), warp tile 32x64, BK=32, ldmatrix frags.
// mode 1 (ABR): K'=384, grid.y: 0->outA, 1->outB(+bias), 2->outR
// mode 3 (UPD-1): K'=768, H = resid + relu(acc+bias), write aug bf16 to outAug
// mode 4 (UPD-2): K'=768, H = resid + relu(acc+bias), red-add into pool[batch]
#define SROW 40
#define SBUFB (128 * SROW * 2)          // 10240 bytes per stage per operand
#define STAGES 3
#define GEMM_SMEM (STAGES * SBUFB * 2)  // 61440 bytes

__device__ __forceinline__ void stage_load(
    int s, int t, int row0, int nrows,
    const __nv_bfloat16* __restrict__ A0, const __nv_bfloat16* __restrict__ A1,
    const __nv_bfloat16* __restrict__ Wp, int wstride,
    uint32_t smbase)
{
    int buf = s % STAGES;
    int kk = (s % 12) * 32;
    int koff = (s / 12) * 384 + kk;
    const __nv_bfloat16* Asrc = (s < 12) ? A0 : A1;
    uint32_t dA = smbase + (uint32_t)buf * SBUFB;
    uint32_t dB = smbase + (uint32_t)(STAGES * SBUFB) + (uint32_t)buf * SBUFB;
    #pragma unroll
    for (int i = t * 2; i < t * 2 + 2; i++) {
        int r = i >> 2, q = i & 3;              // 128 rows x 4 quads
        int gr = row0 + r; if (gr >= nrows) gr = nrows - 1;
        cp_async16(dA + r * 80 + q * 16, Asrc + (size_t)gr * 384 + kk + q * 8);
        cp_async16(dB + r * 80 + q * 16, Wp + (size_t)r * wstride + koff + q * 8);
    }
    cp_commit();
}

__global__ void __launch_bounds__(256)
bmma_gemm(const __nv_bfloat16* __restrict__ A0,
          const __nv_bfloat16* __restrict__ A1,
          const __nv_bfloat16* __restrict__ W, int wstride,
          const float* __restrict__ bias, const float* __restrict__ resid,
          float* __restrict__ outA, float* __restrict__ outB,
          float* __restrict__ outR, __nv_bfloat16* __restrict__ outAug,
          const int* __restrict__ batch, float* __restrict__ pool,
          int nrows, int mode)
{
    extern __shared__ char smraw[];
    uint32_t smbase = smem_u32(smraw);

    int t = threadIdx.x;
    int warp = t >> 5, lane = t & 31;
    int wm = warp & 3, wn = warp >> 2;       // 4 x 2 warp grid
    int g = lane >> 2, tg = lane & 3;
    int row0 = blockIdx.x * 128;
    const __nv_bfloat16* Wp = W + (size_t)(blockIdx.y * 128) * wstride;

    int nsteps = (mode >= 2) ? 24 : 12;

    float acc[2][8][4];
    #pragma unroll
    for (int i = 0; i < 2; i++)
        #pragma unroll
        for (int j = 0; j < 8; j++)
            #pragma unroll
            for (int k = 0; k < 4; k++) acc[i][j][k] = 0.f;

    uint32_t aLane = (uint32_t)(((lane & 15) * SROW + (lane >> 4) * 8) * 2);
    uint32_t bLane = (uint32_t)((((lane >> 4) * 8 + (lane & 7)) * SROW
                               + ((lane >> 3) & 1) * 8) * 2);

    stage_load(0, t, row0, nrows, A0, A1, Wp, wstride, smbase);
    stage_load(1, t, row0, nrows, A0, A1, Wp, wstride, smbase);

    for (int s = 0; s < nsteps; ++s) {
        cp_wait<1>();
        __syncthreads();
        if (s + 2 < nsteps)
            stage_load(s + 2, t, row0, nrows, A0, A1, Wp, wstride, smbase);
        else
            cp_commit();   // empty group keeps wait<1> semantics uniform

        int buf = s % STAGES;
        uint32_t bufA = smbase + (uint32_t)buf * SBUFB;
        uint32_t bufB = smbase + (uint32_t)(STAGES * SBUFB) + (uint32_t)buf * SBUFB;

        #pragma unroll
        for (int ks = 0; ks < 32; ks += 16) {
            uint32_t aF[2][4];
            #pragma unroll
            for (int mi = 0; mi < 2; mi++)
                ldmatrix_x4(aF[mi],
                    bufA + (uint32_t)(((wm * 32 + mi * 16) * SROW + ks) * 2) + aLane);
            uint32_t bF[8][2];
            #pragma unroll
            for (int p = 0; p < 4; p++) {
                uint32_t r[4];
                ldmatrix_x4(r,
                    bufB + (uint32_t)(((wn * 64 + p * 16) * SROW + ks) * 2) + bLane);
                bF[2 * p][0] = r[0]; bF[2 * p][1] = r[1];
                bF[2 * p + 1][0] = r[2]; bF[2 * p + 1][1] = r[3];
            }
            #pragma unroll
            for (int ni = 0; ni < 8; ni++) {
                mma16816(acc[0][ni], aF[0], bF[ni][0], bF[ni][1]);
                mma16816(acc[1][ni], aF[1], bF[ni][0], bF[ni][1]);
            }
        }
        __syncthreads();
    }

    // ---- epilogue ----
    float* dst = outA;
    const float* bi = nullptr;
    const float* rs = nullptr;
    bool dorelu = false;
    if (mode == 1) {
        if (blockIdx.y == 0)      dst = outA;
        else if (blockIdx.y == 1) { dst = outB; bi = bias; }
        else                      dst = outR;
    } else {
        bi = bias; rs = resid; dorelu = true;
    }

    #pragma unroll
    for (int mi = 0; mi < 2; mi++) {
        #pragma unroll
        for (int ni = 0; ni < 8; ni++) {
            int colb = wn * 64 + ni * 8 + tg * 2;
            float bx = 0.f, by = 0.f;
            if (bi) { bx = __ldg(bi + colb); by = __ldg(bi + colb + 1); }
            #pragma unroll
            for (int h = 0; h < 2; h++) {
                int r1 = row0 + wm * 32 + mi * 16 + g + h * 8;
                if (r1 >= nrows) continue;
                float vx = acc[mi][ni][2 * h]     + bx;
                float vy = acc[mi][ni][2 * h + 1] + by;
                if (dorelu) { vx = fmaxf(vx, 0.f); vy = fmaxf(vy, 0.f); }
                if (rs) {
                    vx += rs[(size_t)r1 * HD + colb];
                    vy += rs[(size_t)r1 * HD + colb + 1];
                }
                if (mode == 3) {
                    __nv_bfloat16 hx = __float2bfloat16(vx);
                    __nv_bfloat16 hy = __float2bfloat16(vy);
                    __nv_bfloat162 hh(hx, hy);
                    __nv_bfloat162 ll(
                        __float2bfloat16(vx - __bfloat162float(hx)),
                        __float2bfloat16(vy - __bfloat162float(hy)));
                    __nv_bfloat16* base = outAug + (size_t)r1 * 384;
                    *(uint32_t*)(base + colb)       = *(uint32_t*)&hh;
                    *(uint32_t*)(base + 128 + colb) = *(uint32_t*)&ll;
                    *(uint32_t*)(base + 256 + colb) = *(uint32_t*)&hh;
                } else if (mode == 4) {
                    int gidx = __ldg(batch + r1);
                    red_add_v2(pool + (size_t)gidx * HD + colb, vx, vy);
                } else {
                    *(float2*)(dst + (size_t)r1 * HD + colb) = make_float2(vx, vy);
                }
            }
        }
    }
}

// ---------------- CSR build (hierarchical scan) --------------------------------
__global__ void csr_zero(int* __restrict__ deg, int n) {
    int i = blockIdx.x * blockDim.x + threadIdx.x;
    if (i < n) deg[i] = 0;
}
__global__ void csr_count(const int* __restrict__ col, int* __restrict__ deg,
                          int nedges) {
    int i = blockIdx.x * blockDim.x + threadIdx.x;
    if (i < nedges) atomicAdd(deg + col[i], 1);
}
// phase 1: block-local exclusive scan; per-block total -> part[blockIdx]
__global__ void __launch_bounds__(1024)
csr_scan1(const int* __restrict__ deg, int* __restrict__ off,
          int* __restrict__ part, int n)
{
    __shared__ int wsum[32];
    int t = threadIdx.x, lane = t & 31, w = t >> 5;
    int i = blockIdx.x * 1024 + t;
    int v = (i < n) ? deg[i] : 0;
    int x = v;
    #pragma unroll
    for (int o = 1; o < 32; o <<= 1) {
        int y = __shfl_up_sync(0xFFFFFFFFu, x, o);
        if (lane >= o) x += y;
    }
    if (lane == 31) wsum[w] = x;
    __syncthreads();
    if (w == 0) {
        int s = wsum[lane];
        #pragma unroll
        for (int o = 1; o < 32; o <<= 1) {
            int y = __shfl_up_sync(0xFFFFFFFFu, s, o);
            if (lane >= o) s += y;
        }
        wsum[lane] = s;
    }
    __syncthreads();
    int incl = x + (w > 0 ? wsum[w - 1] : 0);
    if (i < n) off[i] = incl - v;
    if (t == 1023) part[blockIdx.x] = incl;
}
// phase 2: exclusive-scan the <=64 block totals; part[nb] = grand total
__global__ void __launch_bounds__(64)
csr_scan2(int* __restrict__ part, int nb)
{
    __shared__ int w0;
    int t = threadIdx.x, lane = t & 31, w = t >> 5;
    int v = (t < nb) ? part[t] : 0;
    int x = v;
    #pragma unroll
    for (int o = 1; o < 32; o <<= 1) {
        int y = __shfl_up_sync(0xFFFFFFFFu, x, o);
        if (lane >= o) x += y;
    }
    if (w == 0 && lane == 31) w0 = x;
    __syncthreads();
    int incl = x + (w == 1 ? w0 : 0);
    if (t < nb) part[t] = incl - v;
    if (t == 63) part[nb] = incl;
}
// phase 3: add block offsets, produce off/cur and off[n]
__global__ void __launch_bounds__(1024)
csr_scan3(int* __restrict__ off, int* __restrict__ cur,
          const int* __restrict__ part, int n, int nb)
{
    int i = blockIdx.x * 1024 + threadIdx.x;
    if (i < n) {
        int o = off[i] + part[blockIdx.x];
        off[i] = o; cur[i] = o;
    }
    if (i == 0) off[n] = part[nb];
}
__global__ void csr_fill(const int* __restrict__ row, const int* __restrict__ col,
                         const float* __restrict__ dist,
                         int* __restrict__ cur, int* __restrict__ srow,
                         float* __restrict__ sdst, int nedges)
{
    int i = blockIdx.x * blockDim.x + threadIdx.x;
    if (i >= nedges) return;
    int pos = atomicAdd(cur + col[i], 1);
    srow[pos] = row[i];
    sdst[pos] = dist[i];
}

// ---------------- CSR edge aggregation ----------------------------------------
// warp per destination node: aggr = sum over in-edges of relu(A[row]+B'[n]+d*w)
// writes augmented bf16 [hi|lo|hi] directly.
__global__ void __launch_bounds__(256)
edge_csr(const float* __restrict__ A, const float* __restrict__ B,
         const int* __restrict__ off, const int* __restrict__ srow,
         const float* __restrict__ sdst, const float* __restrict__ wd,
         __nv_bfloat16* __restrict__ gaug, int n)
{
    __shared__ __align__(16) float swd[HD];
    int t = threadIdx.x;
    if (t < HD) swd[t] = wd[t];
    __syncthreads();

    int lane = t & 31;
    int node = blockIdx.x * 8 + (t >> 5);
    if (node >= n) return;
    int f = lane * 4;

    float4 w = *(const float4*)(swd + f);
    float4 b = *(const float4*)(B + (size_t)node * HD + f);
    float4 acc = make_float4(0.f, 0.f, 0.f, 0.f);

    int s = __ldg(off + node), e = __ldg(off + node + 1);
    int i = s;
    for (; i + 1 < e; i += 2) {
        int   r0 = __ldg(srow + i),     r1 = __ldg(srow + i + 1);
        float d0 = __ldg(sdst + i),     d1 = __ldg(sdst + i + 1);
        float4 a0 = *(const float4*)(A + (size_t)r0 * HD + f);
        float4 a1 = *(const float4*)(A + (size_t)r1 * HD + f);
        acc.x += fmaxf(fmaf(d0, w.x, a0.x + b.x), 0.f) + fmaxf(fmaf(d1, w.x, a1.x + b.x), 0.f);
        acc.y += fmaxf(fmaf(d0, w.y, a0.y + b.y), 0.f) + fmaxf(fmaf(d1, w.y, a1.y + b.y), 0.f);
        acc.z += fmaxf(fmaf(d0, w.z, a0.z + b.z), 0.f) + fmaxf(fmaf(d1, w.z, a1.z + b.z), 0.f);
        acc.w += fmaxf(fmaf(d0, w.w, a0.w + b.w), 0.f) + fmaxf(fmaf(d1, w.w, a1.w + b.w), 0.f);
    }
    if (i < e) {
        int   r0 = __ldg(srow + i);
        float d0 = __ldg(sdst + i);
        float4 a0 = *(const float4*)(A + (size_t)r0 * HD + f);
        acc.x += fmaxf(fmaf(d0, w.x, a0.x + b.x), 0.f);
        acc.y += fmaxf(fmaf(d0, w.y, a0.y + b.y), 0.f);
        acc.z += fmaxf(fmaf(d0, w.z, a0.z + b.z), 0.f);
        acc.w += fmaxf(fmaf(d0, w.w, a0.w + b.w), 0.f);
    }

    __nv_bfloat16 h0 = __float2bfloat16(acc.x), h1 = __float2bfloat16(acc.y);
    __nv_bfloat16 h2 = __float2bfloat16(acc.z), h3 = __float2bfloat16(acc.w);
    __nv_bfloat162 hh0(h0, h1), hh1(h2, h3);
    __nv_bfloat162 ll0(__float2bfloat16(acc.x - __bfloat162float(h0)),
                       __float2bfloat16(acc.y - __bfloat162float(h1)));
    __nv_bfloat162 ll1(__float2bfloat16(acc.z - __bfloat162float(h2)),
                       __float2bfloat16(acc.w - __bfloat162float(h3)));
    uint2 hb = make_uint2(*(uint32_t*)&hh0, *(uint32_t*)&hh1);
    uint2 lb = make_uint2(*(uint32_t*)&ll0, *(uint32_t*)&ll1);
    __nv_bfloat16* base = gaug + (size_t)node * 384;
    *(uint2*)(base + f)       = hb;
    *(uint2*)(base + 128 + f) = lb;
    *(uint2*)(base + 256 + f) = hb;
}

// ---------------- weight prep: transpose + bf16 hi/lo, augmented layout -------
__global__ void prep_w(const float* __restrict__ wm1, const float* __restrict__ wm2,
                       const float* __restrict__ wr1, const float* __restrict__ wr2,
                       const float* __restrict__ wu1, const float* __restrict__ wu2)
{
    int slot = blockIdx.y;
    int idx = blockIdx.x * 256 + threadIdx.x;
    if (slot < 2) {
        if (idx >= 384 * 384) return;
        int n = idx / 384, k = idx % 384;
        int kb = k & 127, seg = k >> 7;
        const float* wm = slot ? wm2 : wm1;
        const float* wr = slot ? wr2 : wr1;
        float v;
        if (n < 128)       v = wm[kb * 128 + n];
        else if (n < 256)  v = wm[(128 + kb) * 128 + (n - 128)];
        else               v = wr[kb * 128 + (n - 256)];
        __nv_bfloat16 h = __float2bfloat16(v);
        g_wabr[slot][idx] = (seg == 2)
            ? __float2bfloat16(v - __bfloat162float(h)) : h;
    } else {
        if (idx >= 128 * 768) return;
        int n = idx / 768, k = idx % 768;
        int part = k / 384;
        int kb = k & 127, seg = (k % 384) >> 7;
        const float* wu = (slot == 3) ? wu2 : wu1;
        float v = wu[(part * 128 + kb) * 128 + n];
        __nv_bfloat16 h = __float2bfloat16(v);
        g_wupd[slot - 2][idx] = (seg == 2)
            ? __float2bfloat16(v - __bfloat162float(h)) : h;
    }
}

// ---------------- fp32 -> augmented bf16 [hi|lo|hi] ---------------------------
__global__ void conv_split(const float* __restrict__ in,
                           __nv_bfloat16* __restrict__ aug, int ntasks)
{
    int i = blockIdx.x * blockDim.x + threadIdx.x;
    int stride = gridDim.x * blockDim.x;
    for (; i < ntasks; i += stride) {
        int r = i >> 5;
        int c = (i & 31) * 4;
        float4 v = *(const float4*)(in + (size_t)r * HD + c);
        __nv_bfloat16 h0 = __float2bfloat16(v.x), h1 = __float2bfloat16(v.y);
        __nv_bfloat16 h2 = __float2bfloat16(v.z), h3 = __float2bfloat16(v.w);
        __nv_bfloat16 l0 = __float2bfloat16(v.x - __bfloat162float(h0));
        __nv_bfloat16 l1 = __float2bfloat16(v.y - __bfloat162float(h1));
        __nv_bfloat16 l2 = __float2bfloat16(v.z - __bfloat162float(h2));
        __nv_bfloat16 l3 = __float2bfloat16(v.w - __bfloat162float(h3));
        __nv_bfloat162 hh0(h0, h1), hh1(h2, h3), ll0(l0, l1), ll1(l2, l3);
        uint2 hbits = make_uint2(*(uint32_t*)&hh0, *(uint32_t*)&hh1);
        uint2 lbits = make_uint2(*(uint32_t*)&ll0, *(uint32_t*)&ll1);
        __nv_bfloat16* base = aug + (size_t)r * 384;
        *(uint2*)(base + c)       = hbits;
        *(uint2*)(base + 128 + c) = lbits;
        *(uint2*)(base + 256 + c) = hbits;
    }
}

// ---------------- zero kernel -------------------------------------------------
__global__ void zero_kernel(float* __restrict__ p, int n4) {
    int i = blockIdx.x * blockDim.x + threadIdx.x;
    int stride = gridDim.x * blockDim.x;
    float4 z = make_float4(0.f, 0.f, 0.f, 0.f);
    for (; i < n4; i += stride) ((float4*)p)[i] = z;
}

// ---------------- prediction head --------------------------------------------
__global__ void __launch_bounds__(128)
head_kernel(const float* __restrict__ pool,
            const float* __restrict__ wp1, const float* __restrict__ bp1,
            const float* __restrict__ wp2, const float* __restrict__ bp2,
            float* __restrict__ out)
{
    int b = blockIdx.x;
    int t = threadIdx.x;
    __shared__ float sg[HD];
    __shared__ float red[HD];

    sg[t] = pool[(size_t)b * HD + t];
    __syncthreads();

    float acc = bp1[t];
    #pragma unroll 8
    for (int k = 0; k < HD; k++)
        acc = fmaf(sg[k], wp1[(size_t)k * HD + t], acc);
    acc = fmaxf(acc, 0.f) * wp2[t];

    red[t] = acc;
    __syncthreads();
    for (int s = 64; s > 0; s >>= 1) {
        if (t < s) red[t] += red[t + s];
        __syncthreads();
    }
    if (t == 0) out[b] = red[0] + bp2[0];
}

// ---------------- host side ---------------------------------------------------
extern "C" void kernel_launch(void* const* d_in, const int* in_sizes, int n_in,
                              void* d_out, int out_size)
{
    const float* x      = (const float*)d_in[0];
    const float* edist  = (const float*)d_in[1];
    const int*   eidx   = (const int*)  d_in[2];
    const int*   batch  = (const int*)  d_in[3];
    const float* wres1  = (const float*)d_in[4];
    const float* wmsg1  = (const float*)d_in[5];
    const float* bmsg1  = (const float*)d_in[6];
    const float* wupd1  = (const float*)d_in[7];
    const float* bupd1  = (const float*)d_in[8];
    const float* wres2  = (const float*)d_in[9];
    const float* wmsg2  = (const float*)d_in[10];
    const float* bmsg2  = (const float*)d_in[11];
    const float* wupd2  = (const float*)d_in[12];
    const float* bupd2  = (const float*)d_in[13];
    const float* wp1    = (const float*)d_in[14];
    const float* bp1    = (const float*)d_in[15];
    const float* wp2    = (const float*)d_in[16];
    const float* bp2    = (const float*)d_in[17];
    float* out = (float*)d_out;

    int N = in_sizes[0] / HD;
    int E = in_sizes[1];
    int G = out_size;   // T == 1
    const int* erow = eidx;
    const int* ecol = eidx + E;

    float *A, *B, *R, *P;
    __nv_bfloat16 *XAUG, *GAUG, *WABR, *WUPD;
    int *DEG, *OFF, *CUR, *PART, *SROWP; float *SDST;
    cudaGetSymbolAddress((void**)&A,  g_A);
    cudaGetSymbolAddress((void**)&B,  g_Bv);
    cudaGetSymbolAddress((void**)&R,  g_R);
    cudaGetSymbolAddress((void**)&P,  g_pool);
    cudaGetSymbolAddress((void**)&XAUG, g_xaug);
    cudaGetSymbolAddress((void**)&GAUG, g_gaug);
    cudaGetSymbolAddress((void**)&WABR, g_wabr);
    cudaGetSymbolAddress((void**)&WUPD, g_wupd);
    cudaGetSymbolAddress((void**)&DEG, g_deg);
    cudaGetSymbolAddress((void**)&OFF, g_off);
    cudaGetSymbolAddress((void**)&CUR, g_cur);
    cudaGetSymbolAddress((void**)&PART, g_part);
    cudaGetSymbolAddress((void**)&SROWP, g_srow);
    cudaGetSymbolAddress((void**)&SDST, g_sdst);
    __nv_bfloat16* WABR1 = WABR + (size_t)384 * 384;
    __nv_bfloat16* WUPD1 = WUPD + (size_t)128 * 768;

    cudaFuncSetAttribute((const void*)bmma_gemm,
                         cudaFuncAttributeMaxDynamicSharedMemorySize, GEMM_SMEM);

    int nblk = (N + 127) / 128;
    int node_blocks = (N + 7) / 8;
    int nscan = (N + 1023) / 1024;          // <= 64 blocks for N <= 65536

    // weight prep + CSR build (edge structure shared by both layers)
    {
        dim3 gp(576, 4);
        prep_w<<<gp, 256>>>(wmsg1, wmsg2, wres1, wres2, wupd1, wupd2);
    }
    csr_zero<<<(N + 255) / 256, 256>>>(DEG, N);
    csr_count<<<(E + 255) / 256, 256>>>(ecol, DEG, E);
    csr_scan1<<<nscan, 1024>>>(DEG, OFF, PART, N);
    csr_scan2<<<1, 64>>>(PART, nscan);
    csr_scan3<<<nscan, 1024>>>(OFF, CUR, PART, N, nscan);
    csr_fill<<<(E + 255) / 256, 256>>>(erow, ecol, edist, CUR, SROWP, SDST, E);
    zero_kernel<<<4, 256>>>(P, (G * HD) / 4);   // pool accumulators

    dim3 gabr(nblk, 3), g1(nblk, 1);

    // ---------- layer 1 ----------
    conv_split<<<1024, 256>>>(x, XAUG, N * 32);
    bmma_gemm<<<gabr, 256, GEMM_SMEM>>>(XAUG, nullptr, WABR, 384, bmsg1, nullptr,
                                        A, B, R, nullptr, nullptr, nullptr, N, 1);
    edge_csr<<<node_blocks, 256>>>(A, B, OFF, SROWP, SDST, wmsg1 + 256 * HD, GAUG, N);
    // UPD-1: writes layer-2 XAUG directly (in-place safe: block-local rows)
    bmma_gemm<<<g1, 256, GEMM_SMEM>>>(XAUG, GAUG, WUPD, 768, bupd1, R,
                                      nullptr, nullptr, nullptr, XAUG,
                                      nullptr, nullptr, N, 3);

    // ---------- layer 2 ----------
    bmma_gemm<<<gabr, 256, GEMM_SMEM>>>(XAUG, nullptr, WABR1, 384, bmsg2, nullptr,
                                        A, B, R, nullptr, nullptr, nullptr, N, 1);
    edge_csr<<<node_blocks, 256>>>(A, B, OFF, SROWP, SDST, wmsg2 + 256 * HD, GAUG, N);
    // UPD-2: fused pooling — H2 never materialized
    bmma_gemm<<<g1, 256, GEMM_SMEM>>>(XAUG, GAUG, WUPD1, 768, bupd2, R,
                                      nullptr, nullptr, nullptr, nullptr,
                                      batch, P, N, 4);

    // ---------- head ----------
    head_kernel<<<G, 128>>>(P, wp1, bp1, wp2, bp2, out);
}

// round 17
// speedup vs baseline: 1.2548x; 1.0140x over previous
#include <cuda_runtime.h>
#include <cuda_bf16.h>
#include <cstdint>

#define HD 128
#define MAXN 50000
#define MAXE 800000
#define MAXG 64

// ---------------- scratch (static __device__ arrays; no allocation) ----------
__device__ __align__(16) float g_A   [(size_t)MAXN * HD];
__device__ __align__(16) float g_Bv  [(size_t)MAXN * HD];
__device__ __align__(16) float g_R   [(size_t)MAXN * HD];
__device__ __align__(16) float g_pool[(size_t)MAXG * HD];
// dedup augmented bf16 activations: [n, 256] = [hi(128) | lo(128)]
// (GEMM reads logical K'=384 = hi|lo|hi via chunk remapping in stage_load)
__device__ __align__(16) __nv_bfloat16 g_xaug[(size_t)MAXN * 256];
__device__ __align__(16) __nv_bfloat16 g_gaug[(size_t)MAXN * 256];
// augmented weights, [n, k'] row-major (logical layout, unchanged)
__device__ __align__(16) __nv_bfloat16 g_wabr[2][384 * 384];
__device__ __align__(16) __nv_bfloat16 g_wupd[2][128 * 768];
// CSR scratch
__device__ int   g_deg [MAXN];
__device__ int   g_off [MAXN + 1];
__device__ int   g_cur [MAXN];
__device__ int   g_part[80];
__device__ int   g_srow[MAXE];
__device__ float g_sdst[MAXE];

// ---------------- helpers ----------------------------------------------------
__device__ __forceinline__ void red_add_v2(float* dst, float x, float y) {
    asm volatile("red.global.add.v2.f32 [%0], {%1,%2};"
                 :: "l"(dst), "f"(x), "f"(y) : "memory");
}
__device__ __forceinline__ uint32_t smem_u32(const void* p) {
    uint32_t a;
    asm("{ .reg .u64 t; cvta.to.shared.u64 t, %1; cvt.u32.u64 %0, t; }"
        : "=r"(a) : "l"(p));
    return a;
}
__device__ __forceinline__ void cp_async16(uint32_t dst, const void* src) {
    asm volatile("cp.async.ca.shared.global [%0], [%1], 16;"
                 :: "r"(dst), "l"(src) : "memory");
}
__device__ __forceinline__ void cp_commit() {
    asm volatile("cp.async.commit_group;" ::: "memory");
}
template <int N>
__device__ __forceinline__ void cp_wait() {
    asm volatile("cp.async.wait_group %0;" :: "n"(N) : "memory");
}
__device__ __forceinline__ void ldmatrix_x4(uint32_t* r, uint32_t addr) {
    asm volatile("ldmatrix.sync.aligned.m8n8.x4.shared.b16 {%0,%1,%2,%3}, [%4];"
                 : "=r"(r[0]), "=r"(r[1]), "=r"(r[2]), "=r"(r[3]) : "r"(addr));
}
__device__ __forceinline__ void mma16816(float* d, const uint32_t* a,
                                         uint32_t b0, uint32_t b1) {
    asm volatile("mma.sync.aligned.m16n8k16.row.col.f32.bf16.bf16.f32 "
                 "{%0,%1,%2,%3}, {%4,%5,%6,%7}, {%8,%9}, {%0,%1,%2,%3};"
                 : "+f"(d[0]), "+f"(d[1]), "+f"(d[2]), "+f"(d[3])
                 : "r"(a[0]), "r"(a[1]), "r"(a[2]), "r"(a[3]),
                   "r"(b0), "r"(b1));
}

// ---------------- bf16 tensor-core GEMM (3-stage, measured-best) --------------
// 128x128 tile, 8 warps (4m x 2n), warp tile 32x64, BK=32, ldmatrix frags.
// mode 1 (ABR): K'=384, grid.y: 0->outA, 1->outB(+bias), 2->outR
// mode 3 (UPD-1): K'=768, H = resid + relu(acc+bias), write dedup aug to outAug
// mode 4 (UPD-2): K'=768, H = resid + relu(acc+bias), red-add into pool[batch]
#define SROW 40
#define SBUFB (128 * SROW * 2)          // 10240 bytes per stage per operand
#define STAGES 3
#define GEMM_SMEM (STAGES * SBUFB * 2)  // 61440 bytes

__device__ __forceinline__ void stage_load(
    int s, int t, int row0, int nrows,
    const __nv_bfloat16* __restrict__ A0, const __nv_bfloat16* __restrict__ A1,
    const __nv_bfloat16* __restrict__ Wp, int wstride,
    uint32_t smbase)
{
    int buf = s % STAGES;
    int c = s % 12;                     // logical 32-wide chunk within K'=384
    int seg = c >> 2;                   // 0: hi, 1: lo, 2: hi (dedup -> base 0)
    int abase = ((seg == 1) ? 128 : 0) + (c & 3) * 32;   // storage column
    int koff = (s / 12) * 384 + c * 32;                  // weight column
    const __nv_bfloat16* Asrc = (s < 12) ? A0 : A1;
    uint32_t dA = smbase + (uint32_t)buf * SBUFB;
    uint32_t dB = smbase + (uint32_t)(STAGES * SBUFB) + (uint32_t)buf * SBUFB;
    #pragma unroll
    for (int i = t * 2; i < t * 2 + 2; i++) {
        int r = i >> 2, q = i & 3;              // 128 rows x 4 quads
        int gr = row0 + r; if (gr >= nrows) gr = nrows - 1;
        cp_async16(dA + r * 80 + q * 16, Asrc + (size_t)gr * 256 + abase + q * 8);
        cp_async16(dB + r * 80 + q * 16, Wp + (size_t)r * wstride + koff + q * 8);
    }
    cp_commit();
}

__global__ void __launch_bounds__(256)
bmma_gemm(const __nv_bfloat16* __restrict__ A0,
          const __nv_bfloat16* __restrict__ A1,
          const __nv_bfloat16* __restrict__ W, int wstride,
          const float* __restrict__ bias, const float* __restrict__ resid,
          float* __restrict__ outA, float* __restrict__ outB,
          float* __restrict__ outR, __nv_bfloat16* __restrict__ outAug,
          const int* __restrict__ batch, float* __restrict__ pool,
          int nrows, int mode)
{
    extern __shared__ char smraw[];
    uint32_t smbase = smem_u32(smraw);

    int t = threadIdx.x;
    int warp = t >> 5, lane = t & 31;
    int wm = warp & 3, wn = warp >> 2;       // 4 x 2 warp grid
    int g = lane >> 2, tg = lane & 3;
    int row0 = blockIdx.x * 128;
    const __nv_bfloat16* Wp = W + (size_t)(blockIdx.y * 128) * wstride;

    int nsteps = (mode >= 2) ? 24 : 12;

    float acc[2][8][4];
    #pragma unroll
    for (int i = 0; i < 2; i++)
        #pragma unroll
        for (int j = 0; j < 8; j++)
            #pragma unroll
            for (int k = 0; k < 4; k++) acc[i][j][k] = 0.f;

    uint32_t aLane = (uint32_t)(((lane & 15) * SROW + (lane >> 4) * 8) * 2);
    uint32_t bLane = (uint32_t)((((lane >> 4) * 8 + (lane & 7)) * SROW
                               + ((lane >> 3) & 1) * 8) * 2);

    stage_load(0, t, row0, nrows, A0, A1, Wp, wstride, smbase);
    stage_load(1, t, row0, nrows, A0, A1, Wp, wstride, smbase);

    for (int s = 0; s < nsteps; ++s) {
        cp_wait<1>();
        __syncthreads();
        if (s + 2 < nsteps)
            stage_load(s + 2, t, row0, nrows, A0, A1, Wp, wstride, smbase);
        else
            cp_commit();   // empty group keeps wait<1> semantics uniform

        int buf = s % STAGES;
        uint32_t bufA = smbase + (uint32_t)buf * SBUFB;
        uint32_t bufB = smbase + (uint32_t)(STAGES * SBUFB) + (uint32_t)buf * SBUFB;

        #pragma unroll
        for (int ks = 0; ks < 32; ks += 16) {
            uint32_t aF[2][4];
            #pragma unroll
            for (int mi = 0; mi < 2; mi++)
                ldmatrix_x4(aF[mi],
                    bufA + (uint32_t)(((wm * 32 + mi * 16) * SROW + ks) * 2) + aLane);
            uint32_t bF[8][2];
            #pragma unroll
            for (int p = 0; p < 4; p++) {
                uint32_t r[4];
                ldmatrix_x4(r,
                    bufB + (uint32_t)(((wn * 64 + p * 16) * SROW + ks) * 2) + bLane);
                bF[2 * p][0] = r[0]; bF[2 * p][1] = r[1];
                bF[2 * p + 1][0] = r[2]; bF[2 * p + 1][1] = r[3];
            }
            #pragma unroll
            for (int ni = 0; ni < 8; ni++) {
                mma16816(acc[0][ni], aF[0], bF[ni][0], bF[ni][1]);
                mma16816(acc[1][ni], aF[1], bF[ni][0], bF[ni][1]);
            }
        }
        __syncthreads();
    }

    // ---- epilogue ----
    float* dst = outA;
    const float* bi = nullptr;
    const float* rs = nullptr;
    bool dorelu = false;
    if (mode == 1) {
        if (blockIdx.y == 0)      dst = outA;
        else if (blockIdx.y == 1) { dst = outB; bi = bias; }
        else                      dst = outR;
    } else {
        bi = bias; rs = resid; dorelu = true;
    }

    #pragma unroll
    for (int mi = 0; mi < 2; mi++) {
        #pragma unroll
        for (int ni = 0; ni < 8; ni++) {
            int colb = wn * 64 + ni * 8 + tg * 2;
            float bx = 0.f, by = 0.f;
            if (bi) { bx = __ldg(bi + colb); by = __ldg(bi + colb + 1); }
            #pragma unroll
            for (int h = 0; h < 2; h++) {
                int r1 = row0 + wm * 32 + mi * 16 + g + h * 8;
                if (r1 >= nrows) continue;
                float vx = acc[mi][ni][2 * h]     + bx;
                float vy = acc[mi][ni][2 * h + 1] + by;
                if (dorelu) { vx = fmaxf(vx, 0.f); vy = fmaxf(vy, 0.f); }
                if (rs) {
                    vx += rs[(size_t)r1 * HD + colb];
                    vy += rs[(size_t)r1 * HD + colb + 1];
                }
                if (mode == 3) {
                    __nv_bfloat16 hx = __float2bfloat16(vx);
                    __nv_bfloat16 hy = __float2bfloat16(vy);
                    __nv_bfloat162 hh(hx, hy);
                    __nv_bfloat162 ll(
                        __float2bfloat16(vx - __bfloat162float(hx)),
                        __float2bfloat16(vy - __bfloat162float(hy)));
                    __nv_bfloat16* base = outAug + (size_t)r1 * 256;
                    *(uint32_t*)(base + colb)       = *(uint32_t*)&hh;
                    *(uint32_t*)(base + 128 + colb) = *(uint32_t*)&ll;
                } else if (mode == 4) {
                    int gidx = __ldg(batch + r1);
                    red_add_v2(pool + (size_t)gidx * HD + colb, vx, vy);
                } else {
                    *(float2*)(dst + (size_t)r1 * HD + colb) = make_float2(vx, vy);
                }
            }
        }
    }
}

// ---------------- CSR build (hierarchical scan) --------------------------------
__global__ void csr_zero(int* __restrict__ deg, int n) {
    int i = blockIdx.x * blockDim.x + threadIdx.x;
    if (i < n) deg[i] = 0;
}
__global__ void csr_count(const int* __restrict__ col, int* __restrict__ deg,
                          int nedges) {
    int i = blockIdx.x * blockDim.x + threadIdx.x;
    if (i < nedges) atomicAdd(deg + col[i], 1);
}
// phase 1: block-local exclusive scan; per-block total -> part[blockIdx]
__global__ void __launch_bounds__(1024)
csr_scan1(const int* __restrict__ deg, int* __restrict__ off,
          int* __restrict__ part, int n)
{
    __shared__ int wsum[32];
    int t = threadIdx.x, lane = t & 31, w = t >> 5;
    int i = blockIdx.x * 1024 + t;
    int v = (i < n) ? deg[i] : 0;
    int x = v;
    #pragma unroll
    for (int o = 1; o < 32; o <<= 1) {
        int y = __shfl_up_sync(0xFFFFFFFFu, x, o);
        if (lane >= o) x += y;
    }
    if (lane == 31) wsum[w] = x;
    __syncthreads();
    if (w == 0) {
        int s = wsum[lane];
        #pragma unroll
        for (int o = 1; o < 32; o <<= 1) {
            int y = __shfl_up_sync(0xFFFFFFFFu, s, o);
            if (lane >= o) s += y;
        }
        wsum[lane] = s;
    }
    __syncthreads();
    int incl = x + (w > 0 ? wsum[w - 1] : 0);
    if (i < n) off[i] = incl - v;
    if (t == 1023) part[blockIdx.x] = incl;
}
// phase 2: exclusive-scan the <=64 block totals; part[nb] = grand total
__global__ void __launch_bounds__(64)
csr_scan2(int* __restrict__ part, int nb)
{
    __shared__ int w0;
    int t = threadIdx.x, lane = t & 31, w = t >> 5;
    int v = (t < nb) ? part[t] : 0;
    int x = v;
    #pragma unroll
    for (int o = 1; o < 32; o <<= 1) {
        int y = __shfl_up_sync(0xFFFFFFFFu, x, o);
        if (lane >= o) x += y;
    }
    if (w == 0 && lane == 31) w0 = x;
    __syncthreads();
    int incl = x + (w == 1 ? w0 : 0);
    if (t < nb) part[t] = incl - v;
    if (t == 63) part[nb] = incl;
}
// phase 3: add block offsets, produce off/cur and off[n]
__global__ void __launch_bounds__(1024)
csr_scan3(int* __restrict__ off, int* __restrict__ cur,
          const int* __restrict__ part, int n, int nb)
{
    int i = blockIdx.x * 1024 + threadIdx.x;
    if (i < n) {
        int o = off[i] + part[blockIdx.x];
        off[i] = o; cur[i] = o;
    }
    if (i == 0) off[n] = part[nb];
}
__global__ void csr_fill(const int* __restrict__ row, const int* __restrict__ col,
                         const float* __restrict__ dist,
                         int* __restrict__ cur, int* __restrict__ srow,
                         float* __restrict__ sdst, int nedges)
{
    int i = blockIdx.x * blockDim.x + threadIdx.x;
    if (i >= nedges) return;
    int pos = atomicAdd(cur + col[i], 1);
    srow[pos] = row[i];
    sdst[pos] = dist[i];
}

// ---------------- CSR edge aggregation ----------------------------------------
// warp per destination node: aggr = sum over in-edges of relu(A[row]+B'[n]+d*w)
// writes dedup augmented bf16 [hi|lo] directly.
__global__ void __launch_bounds__(256)
edge_csr(const float* __restrict__ A, const float* __restrict__ B,
         const int* __restrict__ off, const int* __restrict__ srow,
         const float* __restrict__ sdst, const float* __restrict__ wd,
         __nv_bfloat16* __restrict__ gaug, int n)
{
    __shared__ __align__(16) float swd[HD];
    int t = threadIdx.x;
    if (t < HD) swd[t] = wd[t];
    __syncthreads();

    int lane = t & 31;
    int node = blockIdx.x * 8 + (t >> 5);
    if (node >= n) return;
    int f = lane * 4;

    float4 w = *(const float4*)(swd + f);
    float4 b = *(const float4*)(B + (size_t)node * HD + f);
    float4 acc = make_float4(0.f, 0.f, 0.f, 0.f);

    int s = __ldg(off + node), e = __ldg(off + node + 1);
    int i = s;
    for (; i + 1 < e; i += 2) {
        int   r0 = __ldg(srow + i),     r1 = __ldg(srow + i + 1);
        float d0 = __ldg(sdst + i),     d1 = __ldg(sdst + i + 1);
        float4 a0 = *(const float4*)(A + (size_t)r0 * HD + f);
        float4 a1 = *(const float4*)(A + (size_t)r1 * HD + f);
        acc.x += fmaxf(fmaf(d0, w.x, a0.x + b.x), 0.f) + fmaxf(fmaf(d1, w.x, a1.x + b.x), 0.f);
        acc.y += fmaxf(fmaf(d0, w.y, a0.y + b.y), 0.f) + fmaxf(fmaf(d1, w.y, a1.y + b.y), 0.f);
        acc.z += fmaxf(fmaf(d0, w.z, a0.z + b.z), 0.f) + fmaxf(fmaf(d1, w.z, a1.z + b.z), 0.f);
        acc.w += fmaxf(fmaf(d0, w.w, a0.w + b.w), 0.f) + fmaxf(fmaf(d1, w.w, a1.w + b.w), 0.f);
    }
    if (i < e) {
        int   r0 = __ldg(srow + i);
        float d0 = __ldg(sdst + i);
        float4 a0 = *(const float4*)(A + (size_t)r0 * HD + f);
        acc.x += fmaxf(fmaf(d0, w.x, a0.x + b.x), 0.f);
        acc.y += fmaxf(fmaf(d0, w.y, a0.y + b.y), 0.f);
        acc.z += fmaxf(fmaf(d0, w.z, a0.z + b.z), 0.f);
        acc.w += fmaxf(fmaf(d0, w.w, a0.w + b.w), 0.f);
    }

    __nv_bfloat16 h0 = __float2bfloat16(acc.x), h1 = __float2bfloat16(acc.y);
    __nv_bfloat16 h2 = __float2bfloat16(acc.z), h3 = __float2bfloat16(acc.w);
    __nv_bfloat162 hh0(h0, h1), hh1(h2, h3);
    __nv_bfloat162 ll0(__float2bfloat16(acc.x - __bfloat162float(h0)),
                       __float2bfloat16(acc.y - __bfloat162float(h1)));
    __nv_bfloat162 ll1(__float2bfloat16(acc.z - __bfloat162float(h2)),
                       __float2bfloat16(acc.w - __bfloat162float(h3)));
    uint2 hb = make_uint2(*(uint32_t*)&hh0, *(uint32_t*)&hh1);
    uint2 lb = make_uint2(*(uint32_t*)&ll0, *(uint32_t*)&ll1);
    __nv_bfloat16* base = gaug + (size_t)node * 256;
    *(uint2*)(base + f)       = hb;
    *(uint2*)(base + 128 + f) = lb;
}

// ---------------- weight prep: transpose + bf16 hi/lo, augmented layout -------
__global__ void prep_w(const float* __restrict__ wm1, const float* __restrict__ wm2,
                       const float* __restrict__ wr1, const float* __restrict__ wr2,
                       const float* __restrict__ wu1, const float* __restrict__ wu2)
{
    int slot = blockIdx.y;
    int idx = blockIdx.x * 256 + threadIdx.x;
    if (slot < 2) {
        if (idx >= 384 * 384) return;
        int n = idx / 384, k = idx % 384;
        int kb = k & 127, seg = k >> 7;
        const float* wm = slot ? wm2 : wm1;
        const float* wr = slot ? wr2 : wr1;
        float v;
        if (n < 128)       v = wm[kb * 128 + n];
        else if (n < 256)  v = wm[(128 + kb) * 128 + (n - 128)];
        else               v = wr[kb * 128 + (n - 256)];
        __nv_bfloat16 h = __float2bfloat16(v);
        g_wabr[slot][idx] = (seg == 2)
            ? __float2bfloat16(v - __bfloat162float(h)) : h;
    } else {
        if (idx >= 128 * 768) return;
        int n = idx / 768, k = idx % 768;
        int part = k / 384;
        int kb = k & 127, seg = (k % 384) >> 7;
        const float* wu = (slot == 3) ? wu2 : wu1;
        float v = wu[(part * 128 + kb) * 128 + n];
        __nv_bfloat16 h = __float2bfloat16(v);
        g_wupd[slot - 2][idx] = (seg == 2)
            ? __float2bfloat16(v - __bfloat162float(h)) : h;
    }
}

// ---------------- fp32 -> dedup augmented bf16 [hi|lo] ------------------------
__global__ void conv_split(const float* __restrict__ in,
                           __nv_bfloat16* __restrict__ aug, int ntasks)
{
    int i = blockIdx.x * blockDim.x + threadIdx.x;
    int stride = gridDim.x * blockDim.x;
    for (; i < ntasks; i += stride) {
        int r = i >> 5;
        int c = (i & 31) * 4;
        float4 v = *(const float4*)(in + (size_t)r * HD + c);
        __nv_bfloat16 h0 = __float2bfloat16(v.x), h1 = __float2bfloat16(v.y);
        __nv_bfloat16 h2 = __float2bfloat16(v.z), h3 = __float2bfloat16(v.w);
        __nv_bfloat16 l0 = __float2bfloat16(v.x - __bfloat162float(h0));
        __nv_bfloat16 l1 = __float2bfloat16(v.y - __bfloat162float(h1));
        __nv_bfloat16 l2 = __float2bfloat16(v.z - __bfloat162float(h2));
        __nv_bfloat16 l3 = __float2bfloat16(v.w - __bfloat162float(h3));
        __nv_bfloat162 hh0(h0, h1), hh1(h2, h3), ll0(l0, l1), ll1(l2, l3);
        uint2 hbits = make_uint2(*(uint32_t*)&hh0, *(uint32_t*)&hh1);
        uint2 lbits = make_uint2(*(uint32_t*)&ll0, *(uint32_t*)&ll1);
        __nv_bfloat16* base = aug + (size_t)r * 256;
        *(uint2*)(base + c)       = hbits;
        *(uint2*)(base + 128 + c) = lbits;
    }
}

// ---------------- zero kernel -------------------------------------------------
__global__ void zero_kernel(float* __restrict__ p, int n4) {
    int i = blockIdx.x * blockDim.x + threadIdx.x;
    int stride = gridDim.x * blockDim.x;
    float4 z = make_float4(0.f, 0.f, 0.f, 0.f);
    for (; i < n4; i += stride) ((float4*)p)[i] = z;
}

// ---------------- prediction head --------------------------------------------
__global__ void __launch_bounds__(128)
head_kernel(const float* __restrict__ pool,
            const float* __restrict__ wp1, const float* __restrict__ bp1,
            const float* __restrict__ wp2, const float* __restrict__ bp2,
            float* __restrict__ out)
{
    int b = blockIdx.x;
    int t = threadIdx.x;
    __shared__ float sg[HD];
    __shared__ float red[HD];

    sg[t] = pool[(size_t)b * HD + t];
    __syncthreads();

    float acc = bp1[t];
    #pragma unroll 8
    for (int k = 0; k < HD; k++)
        acc = fmaf(sg[k], wp1[(size_t)k * HD + t], acc);
    acc = fmaxf(acc, 0.f) * wp2[t];

    red[t] = acc;
    __syncthreads();
    for (int s = 64; s > 0; s >>= 1) {
        if (t < s) red[t] += red[t + s];
        __syncthreads();
    }
    if (t == 0) out[b] = red[0] + bp2[0];
}

// ---------------- host side ---------------------------------------------------
extern "C" void kernel_launch(void* const* d_in, const int* in_sizes, int n_in,
                              void* d_out, int out_size)
{
    const float* x      = (const float*)d_in[0];
    const float* edist  = (const float*)d_in[1];
    const int*   eidx   = (const int*)  d_in[2];
    const int*   batch  = (const int*)  d_in[3];
    const float* wres1  = (const float*)d_in[4];
    const float* wmsg1  = (const float*)d_in[5];
    const float* bmsg1  = (const float*)d_in[6];
    const float* wupd1  = (const float*)d_in[7];
    const float* bupd1  = (const float*)d_in[8];
    const float* wres2  = (const float*)d_in[9];
    const float* wmsg2  = (const float*)d_in[10];
    const float* bmsg2  = (const float*)d_in[11];
    const float* wupd2  = (const float*)d_in[12];
    const float* bupd2  = (const float*)d_in[13];
    const float* wp1    = (const float*)d_in[14];
    const float* bp1    = (const float*)d_in[15];
    const float* wp2    = (const float*)d_in[16];
    const float* bp2    = (const float*)d_in[17];
    float* out = (float*)d_out;

    int N = in_sizes[0] / HD;
    int E = in_sizes[1];
    int G = out_size;   // T == 1
    const int* erow = eidx;
    const int* ecol = eidx + E;

    float *A, *B, *R, *P;
    __nv_bfloat16 *XAUG, *GAUG, *WABR, *WUPD;
    int *DEG, *OFF, *CUR, *PART, *SROWP; float *SDST;
    cudaGetSymbolAddress((void**)&A,  g_A);
    cudaGetSymbolAddress((void**)&B,  g_Bv);
    cudaGetSymbolAddress((void**)&R,  g_R);
    cudaGetSymbolAddress((void**)&P,  g_pool);
    cudaGetSymbolAddress((void**)&XAUG, g_xaug);
    cudaGetSymbolAddress((void**)&GAUG, g_gaug);
    cudaGetSymbolAddress((void**)&WABR, g_wabr);
    cudaGetSymbolAddress((void**)&WUPD, g_wupd);
    cudaGetSymbolAddress((void**)&DEG, g_deg);
    cudaGetSymbolAddress((void**)&OFF, g_off);
    cudaGetSymbolAddress((void**)&CUR, g_cur);
    cudaGetSymbolAddress((void**)&PART, g_part);
    cudaGetSymbolAddress((void**)&SROWP, g_srow);
    cudaGetSymbolAddress((void**)&SDST, g_sdst);
    __nv_bfloat16* WABR1 = WABR + (size_t)384 * 384;
    __nv_bfloat16* WUPD1 = WUPD + (size_t)128 * 768;

    cudaFuncSetAttribute((const void*)bmma_gemm,
                         cudaFuncAttributeMaxDynamicSharedMemorySize, GEMM_SMEM);

    int nblk = (N + 127) / 128;
    int node_blocks = (N + 7) / 8;
    int nscan = (N + 1023) / 1024;          // <= 64 blocks for N <= 65536

    // weight prep + CSR build (edge structure shared by both layers)
    {
        dim3 gp(576, 4);
        prep_w<<<gp, 256>>>(wmsg1, wmsg2, wres1, wres2, wupd1, wupd2);
    }
    csr_zero<<<(N + 255) / 256, 256>>>(DEG, N);
    csr_count<<<(E + 255) / 256, 256>>>(ecol, DEG, E);
    csr_scan1<<<nscan, 1024>>>(DEG, OFF, PART, N);
    csr_scan2<<<1, 64>>>(PART, nscan);
    csr_scan3<<<nscan, 1024>>>(OFF, CUR, PART, N, nscan);
    csr_fill<<<(E + 255) / 256, 256>>>(erow, ecol, edist, CUR, SROWP, SDST, E);
    zero_kernel<<<4, 256>>>(P, (G * HD) / 4);   // pool accumulators

    dim3 gabr(nblk, 3), g1(nblk, 1);

    // ---------- layer 1 ----------
    conv_split<<<1024, 256>>>(x, XAUG, N * 32);
    bmma_gemm<<<gabr, 256, GEMM_SMEM>>>(XAUG, nullptr, WABR, 384, bmsg1, nullptr,
                                        A, B, R, nullptr, nullptr, nullptr, N, 1);
    edge_csr<<<node_blocks, 256>>>(A, B, OFF, SROWP, SDST, wmsg1 + 256 * HD, GAUG, N);
    // UPD-1: writes layer-2 XAUG directly (in-place safe: block-local rows)
    bmma_gemm<<<g1, 256, GEMM_SMEM>>>(XAUG, GAUG, WUPD, 768, bupd1, R,
                                      nullptr, nullptr, nullptr, XAUG,
                                      nullptr, nullptr, N, 3);

    // ---------- layer 2 ----------
    bmma_gemm<<<gabr, 256, GEMM_SMEM>>>(XAUG, nullptr, WABR1, 384, bmsg2, nullptr,
                                        A, B, R, nullptr, nullptr, nullptr, N, 1);
    edge_csr<<<node_blocks, 256>>>(A, B, OFF, SROWP, SDST, wmsg2 + 256 * HD, GAUG, N);
    // UPD-2: fused pooling — H2 never materialized
    bmma_gemm<<<g1, 256, GEMM_SMEM>>>(XAUG, GAUG, WUPD1, 768, bupd2, R,
                                      nullptr, nullptr, nullptr, nullptr,
                                      batch, P, N, 4);

    // ---------- head ----------
    head_kernel<<<G, 128>>>(P, wp1, bp1, wp2, bp2, out);
}